// round 9
// baseline (speedup 1.0000x reference)
#include <cuda_runtime.h>
#include <cuda_fp16.h>
#include <math.h>
#include <stdint.h>

#define BATCH  2
#define SEQ    2048
#define ROWS   (BATCH*SEQ)     // 4096
#define HIDDEN 512
#define QKVP   3584
#define VP     2560
#define HEADS  8
#define HD     64
#define KSPLITS 4
#define KSPLIT  (VP/KSPLITS)   // 640
#define LOG2E  1.4426950408889634f

// ---------------- scratch ----------------
__device__ float  g_xn[(size_t)ROWS*HIDDEN];
__device__ __align__(128) __half g_xth [(size_t)ROWS*HIDDEN];
__device__ __align__(128) __half g_projh[(size_t)ROWS*1536];     // q,k,v
__device__ __align__(128) __half g_cath[(size_t)ROWS*VP];
__device__ __align__(128) __half g_w1t[(size_t)QKVP*HIDDEN];     // [N][K]
__device__ __align__(128) __half g_w2t[(size_t)HIDDEN*VP];       // [N][K]
__device__ float  g_part[(size_t)KSPLITS*ROWS*HIDDEN];           // attn partials, then split-K partials
__device__ float  g_ml[(size_t)BATCH*HEADS*32*4*128];

// ---------------- helpers ----------------
__device__ __forceinline__ uint32_t h2u(float a, float b) {
    __half2 h = __float22half2_rn(make_float2(a, b));
    return *reinterpret_cast<uint32_t*>(&h);
}
__device__ __forceinline__ void mma_f16(float* d, const uint32_t* a, uint32_t b0, uint32_t b1) {
    asm volatile("mma.sync.aligned.m16n8k16.row.col.f32.f16.f16.f32 "
        "{%0,%1,%2,%3}, {%4,%5,%6,%7}, {%8,%9}, {%0,%1,%2,%3};"
        : "+f"(d[0]), "+f"(d[1]), "+f"(d[2]), "+f"(d[3])
        : "r"(a[0]), "r"(a[1]), "r"(a[2]), "r"(a[3]), "r"(b0), "r"(b1));
}
__device__ __forceinline__ void ldsm4(uint32_t* r, uint32_t a) {
    asm volatile("ldmatrix.sync.aligned.m8n8.x4.shared.b16 {%0,%1,%2,%3}, [%4];"
        : "=r"(r[0]), "=r"(r[1]), "=r"(r[2]), "=r"(r[3]) : "r"(a));
}
__device__ __forceinline__ void ldsm4t(uint32_t* r, uint32_t a) {
    asm volatile("ldmatrix.sync.aligned.m8n8.x4.trans.shared.b16 {%0,%1,%2,%3}, [%4];"
        : "=r"(r[0]), "=r"(r[1]), "=r"(r[2]), "=r"(r[3]) : "r"(a));
}
__device__ __forceinline__ void cp16(uint32_t dst, const void* src) {
    asm volatile("cp.async.cg.shared.global [%0], [%1], 16;" :: "r"(dst), "l"(src));
}

// ---------------- weight transpose + fp16 convert: [K][N] f32 -> [N][K] h ----
__global__ void __launch_bounds__(256) trans_cvt_kernel(
    const float* __restrict__ src, __half* __restrict__ dst, int K, int N)
{
    __shared__ __half t[32][33];
    int k0 = blockIdx.x*32, n0 = blockIdx.y*32;
    int tx = threadIdx.x & 31, ty = threadIdx.x >> 5;
    #pragma unroll
    for (int i = 0; i < 32; i += 8)
        t[ty+i][tx] = __float2half_rn(src[(size_t)(k0+ty+i)*N + n0+tx]);
    __syncthreads();
    #pragma unroll
    for (int i = 0; i < 32; i += 8)
        dst[(size_t)(n0+ty+i)*K + k0+tx] = t[tx][ty+i];
}

// ---------------- LayerNorm (+ fused ident copy), vectorized ----------------
__global__ void __launch_bounds__(128) ln_kernel(const float* __restrict__ x,
                                                 const float* __restrict__ gamma,
                                                 const float* __restrict__ beta)
{
    int row = blockIdx.x;
    int tid = threadIdx.x;
    int c0  = tid*4;
    const float* xr = x + (size_t)row*HIDDEN;
    float4 v = *(const float4*)&xr[c0];
    float s = v.x + v.y + v.z + v.w;
    __shared__ float red[4];
    #pragma unroll
    for (int o = 16; o > 0; o >>= 1) s += __shfl_xor_sync(0xffffffffu, s, o);
    if ((tid & 31) == 0) red[tid >> 5] = s;
    __syncthreads();
    float mu = (red[0]+red[1]+red[2]+red[3]) * (1.f/HIDDEN);
    float vs = (v.x-mu)*(v.x-mu) + (v.y-mu)*(v.y-mu) + (v.z-mu)*(v.z-mu) + (v.w-mu)*(v.w-mu);
    #pragma unroll
    for (int o = 16; o > 0; o >>= 1) vs += __shfl_xor_sync(0xffffffffu, vs, o);
    __syncthreads();
    if ((tid & 31) == 0) red[tid >> 5] = vs;
    __syncthreads();
    float var  = (red[0]+red[1]+red[2]+red[3]) * (1.f/HIDDEN);
    float rstd = rsqrtf(var + 1e-5f);
    float4 g = *(const float4*)&gamma[c0];
    float4 bt = *(const float4*)&beta[c0];
    float4 xn;
    xn.x = (v.x-mu)*rstd*g.x + bt.x;
    xn.y = (v.y-mu)*rstd*g.y + bt.y;
    xn.z = (v.z-mu)*rstd*g.z + bt.z;
    xn.w = (v.w-mu)*rstd*g.w + bt.w;
    *(float4*)&g_xn[(size_t)row*HIDDEN + c0] = xn;
    if (c0 < 320) {
        __half2 h0 = __float22half2_rn(make_float2(xn.x, xn.y));
        __half2 h1 = __float22half2_rn(make_float2(xn.z, xn.w));
        uint2 u = make_uint2(*(uint32_t*)&h0, *(uint32_t*)&h1);
        *(uint2*)&g_xth[(size_t)row*HIDDEN + c0] = u;
    }
}

// ---------------- feature transform: shift channels, 16B stores --------------
__global__ void feat_kernel()
{
    int idx = blockIdx.x*256 + threadIdx.x;
    if (idx >= ROWS*16) return;
    int chunk = idx & 15;
    int row   = idx >> 4;
    int c     = 384 + chunk*8;
    int i     = row & (SEQ-1);
    int sh    = (c < 448) ? 1 : 2;
    float4 v0 = make_float4(0.f,0.f,0.f,0.f), v1 = v0;
    if (i >= sh) {
        const float* src = &g_xn[(size_t)(row-sh)*HIDDEN + c];
        v0 = *(const float4*)src;
        v1 = *(const float4*)(src+4);
    }
    __half2 p0 = __float22half2_rn(make_float2(v0.x, v0.y));
    __half2 p1 = __float22half2_rn(make_float2(v0.z, v0.w));
    __half2 p2 = __float22half2_rn(make_float2(v1.x, v1.y));
    __half2 p3 = __float22half2_rn(make_float2(v1.z, v1.w));
    uint4 u = make_uint4(*(uint32_t*)&p0, *(uint32_t*)&p1, *(uint32_t*)&p2, *(uint32_t*)&p3);
    *(uint4*)&g_xth[(size_t)row*HIDDEN + c] = u;
}

// ---------------- cumlogsumexp scan ----------------
__global__ void __launch_bounds__(256) scan_kernel()
{
    int bc  = blockIdx.x;
    int b   = bc >> 6;
    int ch  = 320 + (bc & 63);
    int tid = threadIdx.x;
    int row0 = b*SEQ + tid*8;
    float y[8];
    #pragma unroll
    for (int i = 0; i < 8; i++) y[i] = 5.f * g_xn[(size_t)(row0+i)*HIDDEN + ch];
    float m = -INFINITY, s = 0.f;
    #pragma unroll
    for (int i = 0; i < 8; i++) {
        float M = fmaxf(m, y[i]);
        s = s*expf(m - M) + expf(y[i] - M);
        m = M;
    }
    __shared__ float sm[256], ss[256];
    sm[tid] = m; ss[tid] = s;
    __syncthreads();
    for (int off = 1; off < 256; off <<= 1) {
        float pm = 0.f, ps = 0.f;
        bool act = (tid >= off);
        if (act) { pm = sm[tid-off]; ps = ss[tid-off]; }
        __syncthreads();
        if (act) {
            float M = fmaxf(pm, m);
            s = ps*expf(pm - M) + s*expf(m - M);
            m = M;
            sm[tid] = m; ss[tid] = s;
        }
        __syncthreads();
    }
    float pm = -INFINITY, ps = 0.f;
    if (tid > 0) { pm = sm[tid-1]; ps = ss[tid-1]; }
    #pragma unroll
    for (int i = 0; i < 8; i++) {
        float M = fmaxf(pm, y[i]);
        ps = ps*expf(pm - M) + expf(y[i] - M);
        pm = M;
        g_xth[(size_t)(row0+i)*HIDDEN + ch] = __float2half_rn((pm + logf(ps)) * 0.2f);
    }
}

// ---------------- fp16 tensor GEMM: 128x128 tile, BK=64, ldmatrix + mma.k16 ---
// A [M][K] h, B [N][K] h (both K-contig).
// MODE 1: c<1536 -> g_projh; c>=1536 -> gelu -> g_cath[.., c-1024]
// MODE 2: split-K partials (fp32) -> C + z*ROWS*N
#define AST 72                 // halves/row (144B: 16B mod 128 -> conflict-free ldsm)
#define ASTG (128*AST)
template<int MODE>
__global__ void __launch_bounds__(256, 2) hgemm_kernel(
    const __half* __restrict__ A, const __half* __restrict__ B,
    float* __restrict__ C, int K, int lda, int ldb, int N)
{
    extern __shared__ __half hsm[];

    if (MODE == 2) {
        const int z = blockIdx.z;
        A += (size_t)z*K;
        B += (size_t)z*K;
        C += (size_t)z*ROWS*N;
    }

    const int tid  = threadIdx.x;
    const int warp = tid >> 5;
    const int lane = tid & 31;
    const int gq = lane >> 2;
    const int qd = lane & 3;
    const int warp_m = (warp & 3) * 32;
    const int warp_n = (warp >> 2) * 64;
    const int m0 = blockIdx.y * 128;
    const int n0 = blockIdx.x * 128;
    const int lrow  = lane & 15;
    const int lcol8 = (lane >> 4) * 8;

    const int a_r  = tid >> 1;            // 0..127
    const int a_c8 = (tid & 1) * 8;       // 0 or 8

    const uint32_t as_u = (uint32_t)__cvta_generic_to_shared(hsm);
    const uint32_t bs_u = as_u + (uint32_t)(2*ASTG)*2;
    const uint32_t a_dst0 = as_u + (uint32_t)(a_r*AST + a_c8)*2;
    const uint32_t b_dst0 = bs_u + (uint32_t)(a_r*AST + a_c8)*2;

    const __half* Ag0 = A + (size_t)(m0 + a_r)*lda + a_c8;
    const __half* Bg0 = B + (size_t)(n0 + a_r)*ldb + a_c8;

    const int kTiles = K >> 6;

    #pragma unroll
    for (int s = 0; s < 2; s++) {
        if (s < kTiles) {
            const __half* Ag = Ag0 + s*64;
            const __half* Bg = Bg0 + s*64;
            #pragma unroll
            for (int i = 0; i < 4; i++) {
                cp16(a_dst0 + (uint32_t)(s*ASTG + i*16)*2, Ag + i*16);
                cp16(b_dst0 + (uint32_t)(s*ASTG + i*16)*2, Bg + i*16);
            }
        }
        asm volatile("cp.async.commit_group;");
    }
    asm volatile("cp.async.wait_group 1;");
    __syncthreads();

    float acc[2][8][4];
    #pragma unroll
    for (int mt = 0; mt < 2; mt++)
        #pragma unroll
        for (int nt = 0; nt < 8; nt++)
            #pragma unroll
            for (int i = 0; i < 4; i++) acc[mt][nt][i] = 0.f;

    for (int t = 0; t < kTiles; t++) {
        const int stage = t & 1;
        const uint32_t asb = as_u + (uint32_t)(stage*ASTG)*2;
        const uint32_t bsb = bs_u + (uint32_t)(stage*ASTG)*2;
        #pragma unroll
        for (int kk = 0; kk < 4; kk++) {
            uint32_t af[2][4];
            #pragma unroll
            for (int mt = 0; mt < 2; mt++)
                ldsm4(af[mt], asb + (uint32_t)((warp_m + mt*16 + lrow)*AST + kk*16 + lcol8)*2);
            #pragma unroll
            for (int p = 0; p < 4; p++) {
                uint32_t bf[4];
                ldsm4(bf, bsb + (uint32_t)((warp_n + p*16 + lrow)*AST + kk*16 + lcol8)*2);
                mma_f16(acc[0][2*p],   af[0], bf[0], bf[2]);
                mma_f16(acc[0][2*p+1], af[0], bf[1], bf[3]);
                mma_f16(acc[1][2*p],   af[1], bf[0], bf[2]);
                mma_f16(acc[1][2*p+1], af[1], bf[1], bf[3]);
            }
        }
        if (t + 1 < kTiles) {
            __syncthreads();
            if (t + 2 < kTiles) {
                const __half* Ag = Ag0 + (t+2)*64;
                const __half* Bg = Bg0 + (t+2)*64;
                #pragma unroll
                for (int i = 0; i < 4; i++) {
                    cp16(a_dst0 + (uint32_t)(stage*ASTG + i*16)*2, Ag + i*16);
                    cp16(b_dst0 + (uint32_t)(stage*ASTG + i*16)*2, Bg + i*16);
                }
            }
            asm volatile("cp.async.commit_group;");
            asm volatile("cp.async.wait_group 1;");
            __syncthreads();
        }
    }

    #pragma unroll
    for (int mt = 0; mt < 2; mt++) {
        const int r0 = m0 + warp_m + mt*16 + gq;
        #pragma unroll
        for (int nt = 0; nt < 8; nt++) {
            const int c = n0 + warp_n + nt*8 + 2*qd;
            if (MODE == 1) {
                if (c >= 1536) {
                    #pragma unroll
                    for (int hh = 0; hh < 2; hh++) {
                        int rr = r0 + hh*8;
                        float v0 = acc[mt][nt][hh*2+0], v1 = acc[mt][nt][hh*2+1];
                        float gl0 = 0.5f*v0*(1.f + erff(v0*0.70710678118654752f));
                        float gl1 = 0.5f*v1*(1.f + erff(v1*0.70710678118654752f));
                        *(__half2*)&g_cath[(size_t)rr*VP + (c - 1024)] =
                            __float22half2_rn(make_float2(gl0, gl1));
                    }
                } else {
                    #pragma unroll
                    for (int hh = 0; hh < 2; hh++) {
                        int rr = r0 + hh*8;
                        *(__half2*)&g_projh[(size_t)rr*1536 + c] =
                            __float22half2_rn(make_float2(acc[mt][nt][hh*2+0], acc[mt][nt][hh*2+1]));
                    }
                }
            } else {
                *(float2*)&C[(size_t)r0    *N + c] = make_float2(acc[mt][nt][0], acc[mt][nt][1]);
                *(float2*)&C[(size_t)(r0+8)*N + c] = make_float2(acc[mt][nt][2], acc[mt][nt][3]);
            }
        }
    }
}

// ---------------- split-K reduce + bias ----------------
__global__ void reduce_kernel(float* __restrict__ out, const float* __restrict__ bias)
{
    int i = blockIdx.x*256 + threadIdx.x;
    if (i >= ROWS*HIDDEN/4) return;
    size_t off = (size_t)i*4;
    const size_t stride = (size_t)ROWS*HIDDEN;
    float4 a = *(const float4*)&g_part[off];
    float4 b = *(const float4*)&g_part[off + stride];
    float4 c = *(const float4*)&g_part[off + 2*stride];
    float4 d = *(const float4*)&g_part[off + 3*stride];
    int col = (int)(off & (HIDDEN-1));
    float4 bb = *(const float4*)&bias[col];
    float4 r;
    r.x = a.x + b.x + c.x + d.x + bb.x;
    r.y = a.y + b.y + c.y + d.y + bb.y;
    r.z = a.z + b.z + c.z + d.z + bb.z;
    r.w = a.w + b.w + c.w + d.w + bb.w;
    *(float4*)&out[off] = r;
}

// ---------------- flash attention: fp16 mma, balanced split-K, log2 softmax ---
#define QST 72
#define QTILE (64*QST)
__global__ void __launch_bounds__(128, 4) attn_mma_kernel()
{
    const int qb     = blockIdx.y;
    const int ntiles = qb + 1;
    const int nc     = min(4, (ntiles + 5) / 6);
    const int clen   = (ntiles + nc - 1) / nc;
    const int chunk  = blockIdx.x;
    const int start  = chunk*clen;
    if (start >= ntiles) return;
    const int end    = min(start + clen, ntiles);
    const int nt_loc = end - start;

    extern __shared__ __half asm_[];
    const int bz = blockIdx.z;
    const int h  = bz & 7;
    const int b  = bz >> 3;
    const int q0 = qb*64;
    const int tid  = threadIdx.x;
    const int warp = tid >> 5;
    const int lane = tid & 31;
    const int gq = lane >> 2;
    const int qd = lane & 3;
    const int lrow  = lane & 15;
    const int lcol8 = (lane >> 4) * 8;
    const int vrow  = (lane & 7) + ((lane >> 3) & 1) * 8;

    const float scale2 = 0.125f * LOG2E;           // log2-domain
    const float slope2 = exp2f(-(float)(h+1)) * LOG2E;

    const uint32_t q_u = (uint32_t)__cvta_generic_to_shared(asm_);
    const uint32_t k_u[2] = { q_u + (uint32_t)QTILE*2, q_u + (uint32_t)(3*QTILE)*2 };
    const uint32_t v_u[2] = { q_u + (uint32_t)(2*QTILE)*2, q_u + (uint32_t)(4*QTILE)*2 };

    const int cr  = tid >> 3;
    const int cc8 = (tid & 7) * 8;

    {
        const __half* qb_ = g_projh + (size_t)(b*SEQ + q0 + cr)*1536 + h*HD + cc8;
        #pragma unroll
        for (int i = 0; i < 4; i++)
            cp16(q_u + (uint32_t)((cr + i*16)*QST + cc8)*2, qb_ + (size_t)i*16*1536);
        const __half* kv = g_projh + (size_t)(b*SEQ + start*64 + cr)*1536 + h*HD + cc8;
        #pragma unroll
        for (int i = 0; i < 4; i++) {
            cp16(k_u[0] + (uint32_t)((cr + i*16)*QST + cc8)*2, kv + (size_t)i*16*1536 + 512);
            cp16(v_u[0] + (uint32_t)((cr + i*16)*QST + cc8)*2, kv + (size_t)i*16*1536 + 1024);
        }
        asm volatile("cp.async.commit_group;");
    }
    if (nt_loc > 1) {
        const __half* kv = g_projh + (size_t)(b*SEQ + (start+1)*64 + cr)*1536 + h*HD + cc8;
        #pragma unroll
        for (int i = 0; i < 4; i++) {
            cp16(k_u[1] + (uint32_t)((cr + i*16)*QST + cc8)*2, kv + (size_t)i*16*1536 + 512);
            cp16(v_u[1] + (uint32_t)((cr + i*16)*QST + cc8)*2, kv + (size_t)i*16*1536 + 1024);
        }
    }
    asm volatile("cp.async.commit_group;");
    asm volatile("cp.async.wait_group 1;");
    __syncthreads();

    uint32_t qf[4][4];
    #pragma unroll
    for (int kt = 0; kt < 4; kt++)
        ldsm4(qf[kt], q_u + (uint32_t)((warp*16 + lrow)*QST + kt*16 + lcol8)*2);

    float o[8][4];
    #pragma unroll
    for (int t = 0; t < 8; t++) { o[t][0]=0.f; o[t][1]=0.f; o[t][2]=0.f; o[t][3]=0.f; }
    float m0 = -INFINITY, m1 = -INFINITY, l0 = 0.f, l1 = 0.f;
    const int i0 = q0 + warp*16 + gq;
    const int i1 = i0 + 8;

    for (int lt = 0; lt < nt_loc; lt++) {
        const int j0 = (start + lt)*64;
        const int st = lt & 1;

        float s[8][4];
        #pragma unroll
        for (int t = 0; t < 8; t++) { s[t][0]=0.f; s[t][1]=0.f; s[t][2]=0.f; s[t][3]=0.f; }
        #pragma unroll
        for (int kt = 0; kt < 4; kt++) {
            #pragma unroll
            for (int p = 0; p < 4; p++) {
                uint32_t bf[4];
                ldsm4(bf, k_u[st] + (uint32_t)((p*16 + lrow)*QST + kt*16 + lcol8)*2);
                mma_f16(s[2*p],   qf[kt], bf[0], bf[2]);
                mma_f16(s[2*p+1], qf[kt], bf[1], bf[3]);
            }
        }

        float rm0 = -INFINITY, rm1 = -INFINITY;
        #pragma unroll
        for (int nt = 0; nt < 8; nt++) {
            int j = j0 + nt*8 + 2*qd;
            s[nt][0] = (j   <= i0) ? fmaf(s[nt][0], scale2, slope2*(float)j    ) : -1e30f;
            s[nt][1] = (j+1 <= i0) ? fmaf(s[nt][1], scale2, slope2*(float)(j+1)) : -1e30f;
            s[nt][2] = (j   <= i1) ? fmaf(s[nt][2], scale2, slope2*(float)j    ) : -1e30f;
            s[nt][3] = (j+1 <= i1) ? fmaf(s[nt][3], scale2, slope2*(float)(j+1)) : -1e30f;
            rm0 = fmaxf(rm0, fmaxf(s[nt][0], s[nt][1]));
            rm1 = fmaxf(rm1, fmaxf(s[nt][2], s[nt][3]));
        }
        rm0 = fmaxf(rm0, __shfl_xor_sync(0xffffffffu, rm0, 1));
        rm0 = fmaxf(rm0, __shfl_xor_sync(0xffffffffu, rm0, 2));
        rm1 = fmaxf(rm1, __shfl_xor_sync(0xffffffffu, rm1, 1));
        rm1 = fmaxf(rm1, __shfl_xor_sync(0xffffffffu, rm1, 2));
        float nm0 = fmaxf(m0, rm0), nm1 = fmaxf(m1, rm1);
        float c0 = exp2f(m0 - nm0), c1 = exp2f(m1 - nm1);
        m0 = nm0; m1 = nm1;
        float ps0 = 0.f, ps1 = 0.f;
        #pragma unroll
        for (int nt = 0; nt < 8; nt++) {
            s[nt][0] = exp2f(s[nt][0] - nm0);
            s[nt][1] = exp2f(s[nt][1] - nm0);
            s[nt][2] = exp2f(s[nt][2] - nm1);
            s[nt][3] = exp2f(s[nt][3] - nm1);
            ps0 += s[nt][0] + s[nt][1];
            ps1 += s[nt][2] + s[nt][3];
            o[nt][0] *= c0; o[nt][1] *= c0; o[nt][2] *= c1; o[nt][3] *= c1;
        }
        ps0 += __shfl_xor_sync(0xffffffffu, ps0, 1);
        ps0 += __shfl_xor_sync(0xffffffffu, ps0, 2);
        ps1 += __shfl_xor_sync(0xffffffffu, ps1, 1);
        ps1 += __shfl_xor_sync(0xffffffffu, ps1, 2);
        l0 = l0*c0 + ps0;
        l1 = l1*c1 + ps1;

        #pragma unroll
        for (int c = 0; c < 4; c++) {
            uint32_t pa[4];
            pa[0] = h2u(s[2*c][0],   s[2*c][1]);
            pa[1] = h2u(s[2*c][2],   s[2*c][3]);
            pa[2] = h2u(s[2*c+1][0], s[2*c+1][1]);
            pa[3] = h2u(s[2*c+1][2], s[2*c+1][3]);
            #pragma unroll
            for (int p = 0; p < 4; p++) {
                uint32_t bf[4];
                ldsm4t(bf, v_u[st] + (uint32_t)((c*16 + vrow)*QST + p*16 + lcol8)*2);
                mma_f16(o[2*p],   pa, bf[0], bf[1]);
                mma_f16(o[2*p+1], pa, bf[2], bf[3]);
            }
        }
        __syncthreads();

        if (lt + 1 < nt_loc) {
            if (lt + 2 < nt_loc) {
                const int jn = (start + lt + 2)*64;
                const __half* kv = g_projh + (size_t)(b*SEQ + jn + cr)*1536 + h*HD + cc8;
                #pragma unroll
                for (int i = 0; i < 4; i++) {
                    cp16(k_u[st] + (uint32_t)((cr + i*16)*QST + cc8)*2, kv + (size_t)i*16*1536 + 512);
                    cp16(v_u[st] + (uint32_t)((cr + i*16)*QST + cc8)*2, kv + (size_t)i*16*1536 + 1024);
                }
            }
            asm volatile("cp.async.commit_group;");
            asm volatile("cp.async.wait_group 1;");
            __syncthreads();
        }
    }

    if (nc == 1) {
        float inv0 = 1.f / l0, inv1 = 1.f / l1;
        size_t ob0 = (size_t)(b*SEQ + i0)*VP + h*HD;
        size_t ob1 = (size_t)(b*SEQ + i1)*VP + h*HD;
        #pragma unroll
        for (int nt = 0; nt < 8; nt++) {
            int cl = nt*8 + 2*qd;
            *(__half2*)&g_cath[ob0 + cl] = __float22half2_rn(make_float2(o[nt][0]*inv0, o[nt][1]*inv0));
            *(__half2*)&g_cath[ob1 + cl] = __float22half2_rn(make_float2(o[nt][2]*inv1, o[nt][3]*inv1));
        }
    } else {
        const int pb = (bz*32 + qb)*4 + chunk;
        float* po = g_part + (size_t)pb*4096;
        const int r0 = warp*16 + gq;
        const int r1 = r0 + 8;
        #pragma unroll
        for (int nt = 0; nt < 8; nt++) {
            int cl = nt*8 + 2*qd;
            *(float2*)&po[r0*64 + cl] = make_float2(o[nt][0], o[nt][1]);
            *(float2*)&po[r1*64 + cl] = make_float2(o[nt][2], o[nt][3]);
        }
        if (qd == 0) {
            float* ml = g_ml + (size_t)pb*128;
            ml[r0] = m0;  ml[64 + r0] = l0;
            ml[r1] = m1;  ml[64 + r1] = l1;
        }
    }
}

// ---------------- attention combine (qb >= 6) ----------------
__global__ void __launch_bounds__(256) attn_combine_kernel()
{
    const int qb = 6 + blockIdx.x;        // 6..31
    const int ntiles = qb + 1;
    const int nc = min(4, (ntiles + 5) / 6);
    const int bz = blockIdx.y;
    const int h  = bz & 7;
    const int b  = bz >> 3;
    const int tid = threadIdx.x;
    const int row = tid >> 2;
    const int dg  = (tid & 3) << 4;

    const int pb0 = (bz*32 + qb)*4;
    float mc[4], lc[4];
    float M = -INFINITY;
    for (int c = 0; c < nc; c++) {
        const float* ml = g_ml + (size_t)(pb0 + c)*128;
        mc[c] = ml[row];
        lc[c] = ml[64 + row];
        M = fmaxf(M, mc[c]);
    }
    float L = 0.f;
    float acc[16];
    #pragma unroll
    for (int i = 0; i < 16; i++) acc[i] = 0.f;
    for (int c = 0; c < nc; c++) {
        float w = exp2f(mc[c] - M);      // m stored in log2 domain
        L += lc[c]*w;
        const float* po = g_part + (size_t)(pb0 + c)*4096 + row*64 + dg;
        #pragma unroll
        for (int i = 0; i < 4; i++) {
            float4 v = *(const float4*)&po[i*4];
            acc[i*4+0] += v.x*w; acc[i*4+1] += v.y*w;
            acc[i*4+2] += v.z*w; acc[i*4+3] += v.w*w;
        }
    }
    float inv = 1.f / L;
    __half* dst = g_cath + (size_t)(b*SEQ + qb*64 + row)*VP + h*HD + dg;
    #pragma unroll
    for (int j = 0; j < 8; j++)
        *(__half2*)&dst[j*2] = __float22half2_rn(make_float2(acc[2*j]*inv, acc[2*j+1]*inv));
}

// ---------------- launch ----------------
extern "C" void kernel_launch(void* const* d_in, const int* in_sizes, int n_in,
                              void* d_out, int out_size)
{
    (void)in_sizes; (void)n_in; (void)out_size;
    const float* x     = (const float*)d_in[0];
    const float* gamma = (const float*)d_in[1];
    const float* beta  = (const float*)d_in[2];
    const float* w_in  = (const float*)d_in[3];
    const float* w_out = (const float*)d_in[4];
    const float* b_out = (const float*)d_in[5];
    float* out = (float*)d_out;

    __half *p_xth, *p_w1t, *p_w2t, *p_cath;
    float *p_part;
    cudaGetSymbolAddress((void**)&p_xth,  g_xth);
    cudaGetSymbolAddress((void**)&p_w1t,  g_w1t);
    cudaGetSymbolAddress((void**)&p_w2t,  g_w2t);
    cudaGetSymbolAddress((void**)&p_cath, g_cath);
    cudaGetSymbolAddress((void**)&p_part, g_part);

    trans_cvt_kernel<<<dim3(HIDDEN/32, QKVP/32), 256>>>(w_in,  p_w1t, HIDDEN, QKVP);
    trans_cvt_kernel<<<dim3(VP/32, HIDDEN/32),   256>>>(w_out, p_w2t, VP, HIDDEN);

    ln_kernel<<<ROWS, 128>>>(x, gamma, beta);
    feat_kernel<<<(ROWS*16 + 255)/256, 256>>>();
    scan_kernel<<<BATCH*64, 256>>>();

    int gemm_smem = 4*ASTG*2;                               // 73728
    cudaFuncSetAttribute(hgemm_kernel<1>, cudaFuncAttributeMaxDynamicSharedMemorySize, gemm_smem);
    cudaFuncSetAttribute(hgemm_kernel<2>, cudaFuncAttributeMaxDynamicSharedMemorySize, gemm_smem);

    dim3 g1(QKVP/128, ROWS/128);     // (28, 32)
    hgemm_kernel<1><<<g1, 256, gemm_smem>>>(p_xth, p_w1t, nullptr, HIDDEN, HIDDEN, HIDDEN, QKVP);

    int attn_smem = 5*QTILE*2;                              // 46080
    cudaFuncSetAttribute(attn_mma_kernel, cudaFuncAttributeMaxDynamicSharedMemorySize, attn_smem);
    attn_mma_kernel<<<dim3(4, SEQ/64, BATCH*HEADS), 128, attn_smem>>>();
    attn_combine_kernel<<<dim3(26, BATCH*HEADS), 256>>>();

    dim3 g2(HIDDEN/128, ROWS/128, KSPLITS);  // (4, 32, 4)
    hgemm_kernel<2><<<g2, 256, gemm_smem>>>(p_cath, p_w2t, p_part, KSPLIT, VP, VP, HIDDEN);
    reduce_kernel<<<(ROWS*HIDDEN/4 + 255)/256, 256>>>(out, b_out);
}

// round 11
// speedup vs baseline: 1.1064x; 1.1064x over previous
#include <cuda_runtime.h>
#include <cuda_fp16.h>
#include <math.h>
#include <stdint.h>

#define BATCH  2
#define SEQ    2048
#define ROWS   (BATCH*SEQ)     // 4096
#define HIDDEN 512
#define QKVP   3584
#define VP     2560
#define HEADS  8
#define HD     64
#define KSPLITS 4
#define KSPLIT  (VP/KSPLITS)   // 640
#define CHUNK_TILES 8
#define LOG2E  1.4426950408889634f

// ---------------- scratch ----------------
__device__ float  g_xn[(size_t)ROWS*HIDDEN];
__device__ __align__(128) __half g_xth [(size_t)ROWS*HIDDEN];
__device__ __align__(128) __half g_projh[(size_t)ROWS*1536];     // q,k,v
__device__ __align__(128) __half g_cath[(size_t)ROWS*VP];
__device__ __align__(128) __half g_w1t[(size_t)QKVP*HIDDEN];     // [N][K]
__device__ __align__(128) __half g_w2t[(size_t)HIDDEN*VP];       // [N][K]
__device__ float  g_part[(size_t)KSPLITS*ROWS*HIDDEN];           // attn partials, then split-K partials
__device__ float  g_ml[(size_t)BATCH*HEADS*32*4*128];

// ---------------- helpers ----------------
__device__ __forceinline__ uint32_t h2u(float a, float b) {
    __half2 h = __float22half2_rn(make_float2(a, b));
    return *reinterpret_cast<uint32_t*>(&h);
}
__device__ __forceinline__ void mma_f16(float* d, const uint32_t* a, uint32_t b0, uint32_t b1) {
    asm volatile("mma.sync.aligned.m16n8k16.row.col.f32.f16.f16.f32 "
        "{%0,%1,%2,%3}, {%4,%5,%6,%7}, {%8,%9}, {%0,%1,%2,%3};"
        : "+f"(d[0]), "+f"(d[1]), "+f"(d[2]), "+f"(d[3])
        : "r"(a[0]), "r"(a[1]), "r"(a[2]), "r"(a[3]), "r"(b0), "r"(b1));
}
__device__ __forceinline__ void ldsm4(uint32_t* r, uint32_t a) {
    asm volatile("ldmatrix.sync.aligned.m8n8.x4.shared.b16 {%0,%1,%2,%3}, [%4];"
        : "=r"(r[0]), "=r"(r[1]), "=r"(r[2]), "=r"(r[3]) : "r"(a));
}
__device__ __forceinline__ void ldsm4t(uint32_t* r, uint32_t a) {
    asm volatile("ldmatrix.sync.aligned.m8n8.x4.trans.shared.b16 {%0,%1,%2,%3}, [%4];"
        : "=r"(r[0]), "=r"(r[1]), "=r"(r[2]), "=r"(r[3]) : "r"(a));
}
__device__ __forceinline__ void cp16(uint32_t dst, const void* src) {
    asm volatile("cp.async.cg.shared.global [%0], [%1], 16;" :: "r"(dst), "l"(src));
}

// ---------------- weight transpose + fp16 convert: [K][N] f32 -> [N][K] h ----
__global__ void __launch_bounds__(256) trans_cvt_kernel(
    const float* __restrict__ src, __half* __restrict__ dst, int K, int N)
{
    __shared__ __half t[32][33];
    int k0 = blockIdx.x*32, n0 = blockIdx.y*32;
    int tx = threadIdx.x & 31, ty = threadIdx.x >> 5;
    #pragma unroll
    for (int i = 0; i < 32; i += 8)
        t[ty+i][tx] = __float2half_rn(src[(size_t)(k0+ty+i)*N + n0+tx]);
    __syncthreads();
    #pragma unroll
    for (int i = 0; i < 32; i += 8)
        dst[(size_t)(n0+ty+i)*K + k0+tx] = t[tx][ty+i];
}

// ---------------- LayerNorm (+ fused ident copy), vectorized ----------------
__global__ void __launch_bounds__(128) ln_kernel(const float* __restrict__ x,
                                                 const float* __restrict__ gamma,
                                                 const float* __restrict__ beta)
{
    int row = blockIdx.x;
    int tid = threadIdx.x;
    int c0  = tid*4;
    const float* xr = x + (size_t)row*HIDDEN;
    float4 v = *(const float4*)&xr[c0];
    float s = v.x + v.y + v.z + v.w;
    __shared__ float red[4];
    #pragma unroll
    for (int o = 16; o > 0; o >>= 1) s += __shfl_xor_sync(0xffffffffu, s, o);
    if ((tid & 31) == 0) red[tid >> 5] = s;
    __syncthreads();
    float mu = (red[0]+red[1]+red[2]+red[3]) * (1.f/HIDDEN);
    float vs = (v.x-mu)*(v.x-mu) + (v.y-mu)*(v.y-mu) + (v.z-mu)*(v.z-mu) + (v.w-mu)*(v.w-mu);
    #pragma unroll
    for (int o = 16; o > 0; o >>= 1) vs += __shfl_xor_sync(0xffffffffu, vs, o);
    __syncthreads();
    if ((tid & 31) == 0) red[tid >> 5] = vs;
    __syncthreads();
    float var  = (red[0]+red[1]+red[2]+red[3]) * (1.f/HIDDEN);
    float rstd = rsqrtf(var + 1e-5f);
    float4 g = *(const float4*)&gamma[c0];
    float4 bt = *(const float4*)&beta[c0];
    float4 xn;
    xn.x = (v.x-mu)*rstd*g.x + bt.x;
    xn.y = (v.y-mu)*rstd*g.y + bt.y;
    xn.z = (v.z-mu)*rstd*g.z + bt.z;
    xn.w = (v.w-mu)*rstd*g.w + bt.w;
    *(float4*)&g_xn[(size_t)row*HIDDEN + c0] = xn;
    if (c0 < 320) {
        __half2 h0 = __float22half2_rn(make_float2(xn.x, xn.y));
        __half2 h1 = __float22half2_rn(make_float2(xn.z, xn.w));
        uint2 u = make_uint2(*(uint32_t*)&h0, *(uint32_t*)&h1);
        *(uint2*)&g_xth[(size_t)row*HIDDEN + c0] = u;
    }
}

// ---------------- feature transform: shift channels, 16B stores --------------
__global__ void feat_kernel()
{
    int idx = blockIdx.x*256 + threadIdx.x;
    if (idx >= ROWS*16) return;
    int chunk = idx & 15;
    int row   = idx >> 4;
    int c     = 384 + chunk*8;
    int i     = row & (SEQ-1);
    int sh    = (c < 448) ? 1 : 2;
    float4 v0 = make_float4(0.f,0.f,0.f,0.f), v1 = v0;
    if (i >= sh) {
        const float* src = &g_xn[(size_t)(row-sh)*HIDDEN + c];
        v0 = *(const float4*)src;
        v1 = *(const float4*)(src+4);
    }
    __half2 p0 = __float22half2_rn(make_float2(v0.x, v0.y));
    __half2 p1 = __float22half2_rn(make_float2(v0.z, v0.w));
    __half2 p2 = __float22half2_rn(make_float2(v1.x, v1.y));
    __half2 p3 = __float22half2_rn(make_float2(v1.z, v1.w));
    uint4 u = make_uint4(*(uint32_t*)&p0, *(uint32_t*)&p1, *(uint32_t*)&p2, *(uint32_t*)&p3);
    *(uint4*)&g_xth[(size_t)row*HIDDEN + c] = u;
}

// ---------------- cumlogsumexp scan ----------------
__global__ void __launch_bounds__(256) scan_kernel()
{
    int bc  = blockIdx.x;
    int b   = bc >> 6;
    int ch  = 320 + (bc & 63);
    int tid = threadIdx.x;
    int row0 = b*SEQ + tid*8;
    float y[8];
    #pragma unroll
    for (int i = 0; i < 8; i++) y[i] = 5.f * g_xn[(size_t)(row0+i)*HIDDEN + ch];
    float m = -INFINITY, s = 0.f;
    #pragma unroll
    for (int i = 0; i < 8; i++) {
        float M = fmaxf(m, y[i]);
        s = s*expf(m - M) + expf(y[i] - M);
        m = M;
    }
    __shared__ float sm[256], ss[256];
    sm[tid] = m; ss[tid] = s;
    __syncthreads();
    for (int off = 1; off < 256; off <<= 1) {
        float pm = 0.f, ps = 0.f;
        bool act = (tid >= off);
        if (act) { pm = sm[tid-off]; ps = ss[tid-off]; }
        __syncthreads();
        if (act) {
            float M = fmaxf(pm, m);
            s = ps*expf(pm - M) + s*expf(m - M);
            m = M;
            sm[tid] = m; ss[tid] = s;
        }
        __syncthreads();
    }
    float pm = -INFINITY, ps = 0.f;
    if (tid > 0) { pm = sm[tid-1]; ps = ss[tid-1]; }
    #pragma unroll
    for (int i = 0; i < 8; i++) {
        float M = fmaxf(pm, y[i]);
        ps = ps*expf(pm - M) + expf(y[i] - M);
        pm = M;
        g_xth[(size_t)(row0+i)*HIDDEN + ch] = __float2half_rn((pm + logf(ps)) * 0.2f);
    }
}

// ---------------- fp16 tensor GEMM: 128x128 tile, BK=32 (R8-proven) ----------
#define AST 40                 // halves per row (80B: 5r mod 8 -> conflict-free ldsm)
#define ASTG (128*AST)
template<int MODE>
__global__ void __launch_bounds__(256, 2) hgemm_kernel(
    const __half* __restrict__ A, const __half* __restrict__ B,
    float* __restrict__ C, int K, int lda, int ldb, int N)
{
    extern __shared__ __half hsm[];
    __half* As = hsm;
    __half* Bs = hsm + 2*ASTG;

    if (MODE == 2) {
        const int z = blockIdx.z;
        A += (size_t)z*K;
        B += (size_t)z*K;
        C += (size_t)z*ROWS*N;
    }

    const int tid  = threadIdx.x;
    const int warp = tid >> 5;
    const int lane = tid & 31;
    const int gq = lane >> 2;
    const int qd = lane & 3;
    const int warp_m = (warp & 3) * 32;
    const int warp_n = (warp >> 2) * 64;
    const int m0 = blockIdx.y * 128;
    const int n0 = blockIdx.x * 128;
    const int lrow  = lane & 15;
    const int lcol8 = (lane >> 4) * 8;

    const int a_r  = tid >> 2;
    const int a_c8 = (tid & 3) * 8;

    const uint32_t as_u = (uint32_t)__cvta_generic_to_shared(As);
    const uint32_t bs_u = (uint32_t)__cvta_generic_to_shared(Bs);
    const uint32_t a_dst0 = as_u + (uint32_t)(a_r*AST + a_c8)*2;
    const uint32_t b_dst0 = bs_u + (uint32_t)(a_r*AST + a_c8)*2;

    const __half* Ag0 = A + (size_t)(m0 + a_r)*lda + a_c8;
    const __half* Bg0 = B + (size_t)(n0 + a_r)*ldb + a_c8;

    const int kTiles = K >> 5;

    #pragma unroll
    for (int s = 0; s < 2; s++) {
        if (s < kTiles) {
            const __half* Ag = Ag0 + s*32;
            const __half* Bg = Bg0 + s*32;
            #pragma unroll
            for (int i = 0; i < 2; i++) {
                cp16(a_dst0 + (uint32_t)(s*ASTG + i*64*AST)*2, Ag + (size_t)i*64*lda);
                cp16(b_dst0 + (uint32_t)(s*ASTG + i*64*AST)*2, Bg + (size_t)i*64*ldb);
            }
        }
        asm volatile("cp.async.commit_group;");
    }
    asm volatile("cp.async.wait_group 1;");
    __syncthreads();

    float acc[2][8][4];
    #pragma unroll
    for (int mt = 0; mt < 2; mt++)
        #pragma unroll
        for (int nt = 0; nt < 8; nt++)
            #pragma unroll
            for (int i = 0; i < 4; i++) acc[mt][nt][i] = 0.f;

    for (int t = 0; t < kTiles; t++) {
        const int stage = t & 1;
        const uint32_t asb = as_u + (uint32_t)(stage*ASTG)*2;
        const uint32_t bsb = bs_u + (uint32_t)(stage*ASTG)*2;
        #pragma unroll
        for (int kk = 0; kk < 2; kk++) {
            uint32_t af[2][4];
            #pragma unroll
            for (int mt = 0; mt < 2; mt++)
                ldsm4(af[mt], asb + (uint32_t)((warp_m + mt*16 + lrow)*AST + kk*16 + lcol8)*2);
            #pragma unroll
            for (int p = 0; p < 4; p++) {
                uint32_t bf[4];
                ldsm4(bf, bsb + (uint32_t)((warp_n + p*16 + lrow)*AST + kk*16 + lcol8)*2);
                mma_f16(acc[0][2*p],   af[0], bf[0], bf[2]);
                mma_f16(acc[0][2*p+1], af[0], bf[1], bf[3]);
                mma_f16(acc[1][2*p],   af[1], bf[0], bf[2]);
                mma_f16(acc[1][2*p+1], af[1], bf[1], bf[3]);
            }
        }
        if (t + 1 < kTiles) {
            __syncthreads();
            if (t + 2 < kTiles) {
                const __half* Ag = Ag0 + (t+2)*32;
                const __half* Bg = Bg0 + (t+2)*32;
                #pragma unroll
                for (int i = 0; i < 2; i++) {
                    cp16(a_dst0 + (uint32_t)(stage*ASTG + i*64*AST)*2, Ag + (size_t)i*64*lda);
                    cp16(b_dst0 + (uint32_t)(stage*ASTG + i*64*AST)*2, Bg + (size_t)i*64*ldb);
                }
            }
            asm volatile("cp.async.commit_group;");
            asm volatile("cp.async.wait_group 1;");
            __syncthreads();
        }
    }

    #pragma unroll
    for (int mt = 0; mt < 2; mt++) {
        const int r0 = m0 + warp_m + mt*16 + gq;
        #pragma unroll
        for (int nt = 0; nt < 8; nt++) {
            const int c = n0 + warp_n + nt*8 + 2*qd;
            if (MODE == 1) {
                if (c >= 1536) {
                    #pragma unroll
                    for (int hh = 0; hh < 2; hh++) {
                        int rr = r0 + hh*8;
                        float v0 = acc[mt][nt][hh*2+0], v1 = acc[mt][nt][hh*2+1];
                        float gl0 = 0.5f*v0*(1.f + erff(v0*0.70710678118654752f));
                        float gl1 = 0.5f*v1*(1.f + erff(v1*0.70710678118654752f));
                        *(__half2*)&g_cath[(size_t)rr*VP + (c - 1024)] =
                            __float22half2_rn(make_float2(gl0, gl1));
                    }
                } else {
                    #pragma unroll
                    for (int hh = 0; hh < 2; hh++) {
                        int rr = r0 + hh*8;
                        *(__half2*)&g_projh[(size_t)rr*1536 + c] =
                            __float22half2_rn(make_float2(acc[mt][nt][hh*2+0], acc[mt][nt][hh*2+1]));
                    }
                }
            } else {
                *(float2*)&C[(size_t)r0    *N + c] = make_float2(acc[mt][nt][0], acc[mt][nt][1]);
                *(float2*)&C[(size_t)(r0+8)*N + c] = make_float2(acc[mt][nt][2], acc[mt][nt][3]);
            }
        }
    }
}

// ---------------- split-K reduce + bias ----------------
__global__ void reduce_kernel(float* __restrict__ out, const float* __restrict__ bias)
{
    int i = blockIdx.x*256 + threadIdx.x;
    if (i >= ROWS*HIDDEN/4) return;
    size_t off = (size_t)i*4;
    const size_t stride = (size_t)ROWS*HIDDEN;
    float4 a = *(const float4*)&g_part[off];
    float4 b = *(const float4*)&g_part[off + stride];
    float4 c = *(const float4*)&g_part[off + 2*stride];
    float4 d = *(const float4*)&g_part[off + 3*stride];
    int col = (int)(off & (HIDDEN-1));
    float4 bb = *(const float4*)&bias[col];
    float4 r;
    r.x = a.x + b.x + c.x + d.x + bb.x;
    r.y = a.y + b.y + c.y + d.y + bb.y;
    r.z = a.z + b.z + c.z + d.z + bb.z;
    r.w = a.w + b.w + c.w + d.w + bb.w;
    *(float4*)&out[off] = r;
}

// ---------------- flash attention: fp16 mma, split-K (R8), log2 softmax ------
#define QST 72
#define QTILE (64*QST)
__global__ void __launch_bounds__(128, 4) attn_mma_kernel()
{
    const int qb     = blockIdx.y;
    const int ntiles = qb + 1;
    const int chunk  = blockIdx.x;
    const int start  = chunk*CHUNK_TILES;
    if (start >= ntiles) return;
    const int end    = min(start + CHUNK_TILES, ntiles);
    const int nc     = (ntiles + CHUNK_TILES - 1) / CHUNK_TILES;
    const int nt_loc = end - start;

    extern __shared__ __half asm_[];
    const int bz = blockIdx.z;
    const int h  = bz & 7;
    const int b  = bz >> 3;
    const int q0 = qb*64;
    const int tid  = threadIdx.x;
    const int warp = tid >> 5;
    const int lane = tid & 31;
    const int gq = lane >> 2;
    const int qd = lane & 3;
    const int lrow  = lane & 15;
    const int lcol8 = (lane >> 4) * 8;
    const int vrow  = (lane & 7) + ((lane >> 3) & 1) * 8;

    const float scale2 = 0.125f * LOG2E;
    const float slope2 = exp2f(-(float)(h+1)) * LOG2E;

    const uint32_t q_u = (uint32_t)__cvta_generic_to_shared(asm_);
    const uint32_t k_u[2] = { q_u + (uint32_t)QTILE*2, q_u + (uint32_t)(3*QTILE)*2 };
    const uint32_t v_u[2] = { q_u + (uint32_t)(2*QTILE)*2, q_u + (uint32_t)(4*QTILE)*2 };

    const int cr  = tid >> 3;
    const int cc8 = (tid & 7) * 8;

    {
        const __half* qb_ = g_projh + (size_t)(b*SEQ + q0 + cr)*1536 + h*HD + cc8;
        #pragma unroll
        for (int i = 0; i < 4; i++)
            cp16(q_u + (uint32_t)((cr + i*16)*QST + cc8)*2, qb_ + (size_t)i*16*1536);
        const __half* kv = g_projh + (size_t)(b*SEQ + start*64 + cr)*1536 + h*HD + cc8;
        #pragma unroll
        for (int i = 0; i < 4; i++) {
            cp16(k_u[0] + (uint32_t)((cr + i*16)*QST + cc8)*2, kv + (size_t)i*16*1536 + 512);
            cp16(v_u[0] + (uint32_t)((cr + i*16)*QST + cc8)*2, kv + (size_t)i*16*1536 + 1024);
        }
        asm volatile("cp.async.commit_group;");
    }
    if (nt_loc > 1) {
        const __half* kv = g_projh + (size_t)(b*SEQ + (start+1)*64 + cr)*1536 + h*HD + cc8;
        #pragma unroll
        for (int i = 0; i < 4; i++) {
            cp16(k_u[1] + (uint32_t)((cr + i*16)*QST + cc8)*2, kv + (size_t)i*16*1536 + 512);
            cp16(v_u[1] + (uint32_t)((cr + i*16)*QST + cc8)*2, kv + (size_t)i*16*1536 + 1024);
        }
    }
    asm volatile("cp.async.commit_group;");
    asm volatile("cp.async.wait_group 1;");
    __syncthreads();

    uint32_t qf[4][4];
    #pragma unroll
    for (int kt = 0; kt < 4; kt++)
        ldsm4(qf[kt], q_u + (uint32_t)((warp*16 + lrow)*QST + kt*16 + lcol8)*2);

    float o[8][4];
    #pragma unroll
    for (int t = 0; t < 8; t++) { o[t][0]=0.f; o[t][1]=0.f; o[t][2]=0.f; o[t][3]=0.f; }
    float m0 = -INFINITY, m1 = -INFINITY, l0 = 0.f, l1 = 0.f;
    const int i0 = q0 + warp*16 + gq;
    const int i1 = i0 + 8;

    for (int lt = 0; lt < nt_loc; lt++) {
        const int j0 = (start + lt)*64;
        const int st = lt & 1;

        float s[8][4];
        #pragma unroll
        for (int t = 0; t < 8; t++) { s[t][0]=0.f; s[t][1]=0.f; s[t][2]=0.f; s[t][3]=0.f; }
        #pragma unroll
        for (int kt = 0; kt < 4; kt++) {
            #pragma unroll
            for (int p = 0; p < 4; p++) {
                uint32_t bf[4];
                ldsm4(bf, k_u[st] + (uint32_t)((p*16 + lrow)*QST + kt*16 + lcol8)*2);
                mma_f16(s[2*p],   qf[kt], bf[0], bf[2]);
                mma_f16(s[2*p+1], qf[kt], bf[1], bf[3]);
            }
        }

        float rm0 = -INFINITY, rm1 = -INFINITY;
        #pragma unroll
        for (int nt = 0; nt < 8; nt++) {
            int j = j0 + nt*8 + 2*qd;
            s[nt][0] = (j   <= i0) ? fmaf(s[nt][0], scale2, slope2*(float)j    ) : -1e30f;
            s[nt][1] = (j+1 <= i0) ? fmaf(s[nt][1], scale2, slope2*(float)(j+1)) : -1e30f;
            s[nt][2] = (j   <= i1) ? fmaf(s[nt][2], scale2, slope2*(float)j    ) : -1e30f;
            s[nt][3] = (j+1 <= i1) ? fmaf(s[nt][3], scale2, slope2*(float)(j+1)) : -1e30f;
            rm0 = fmaxf(rm0, fmaxf(s[nt][0], s[nt][1]));
            rm1 = fmaxf(rm1, fmaxf(s[nt][2], s[nt][3]));
        }
        rm0 = fmaxf(rm0, __shfl_xor_sync(0xffffffffu, rm0, 1));
        rm0 = fmaxf(rm0, __shfl_xor_sync(0xffffffffu, rm0, 2));
        rm1 = fmaxf(rm1, __shfl_xor_sync(0xffffffffu, rm1, 1));
        rm1 = fmaxf(rm1, __shfl_xor_sync(0xffffffffu, rm1, 2));
        float nm0 = fmaxf(m0, rm0), nm1 = fmaxf(m1, rm1);
        float c0 = exp2f(m0 - nm0), c1 = exp2f(m1 - nm1);
        m0 = nm0; m1 = nm1;
        float ps0 = 0.f, ps1 = 0.f;
        #pragma unroll
        for (int nt = 0; nt < 8; nt++) {
            s[nt][0] = exp2f(s[nt][0] - nm0);
            s[nt][1] = exp2f(s[nt][1] - nm0);
            s[nt][2] = exp2f(s[nt][2] - nm1);
            s[nt][3] = exp2f(s[nt][3] - nm1);
            ps0 += s[nt][0] + s[nt][1];
            ps1 += s[nt][2] + s[nt][3];
            o[nt][0] *= c0; o[nt][1] *= c0; o[nt][2] *= c1; o[nt][3] *= c1;
        }
        ps0 += __shfl_xor_sync(0xffffffffu, ps0, 1);
        ps0 += __shfl_xor_sync(0xffffffffu, ps0, 2);
        ps1 += __shfl_xor_sync(0xffffffffu, ps1, 1);
        ps1 += __shfl_xor_sync(0xffffffffu, ps1, 2);
        l0 = l0*c0 + ps0;
        l1 = l1*c1 + ps1;

        #pragma unroll
        for (int c = 0; c < 4; c++) {
            uint32_t pa[4];
            pa[0] = h2u(s[2*c][0],   s[2*c][1]);
            pa[1] = h2u(s[2*c][2],   s[2*c][3]);
            pa[2] = h2u(s[2*c+1][0], s[2*c+1][1]);
            pa[3] = h2u(s[2*c+1][2], s[2*c+1][3]);
            #pragma unroll
            for (int p = 0; p < 4; p++) {
                uint32_t bf[4];
                ldsm4t(bf, v_u[st] + (uint32_t)((c*16 + vrow)*QST + p*16 + lcol8)*2);
                mma_f16(o[2*p],   pa, bf[0], bf[1]);
                mma_f16(o[2*p+1], pa, bf[2], bf[3]);
            }
        }
        __syncthreads();

        if (lt + 1 < nt_loc) {
            if (lt + 2 < nt_loc) {
                const int jn = (start + lt + 2)*64;
                const __half* kv = g_projh + (size_t)(b*SEQ + jn + cr)*1536 + h*HD + cc8;
                #pragma unroll
                for (int i = 0; i < 4; i++) {
                    cp16(k_u[st] + (uint32_t)((cr + i*16)*QST + cc8)*2, kv + (size_t)i*16*1536 + 512);
                    cp16(v_u[st] + (uint32_t)((cr + i*16)*QST + cc8)*2, kv + (size_t)i*16*1536 + 1024);
                }
            }
            asm volatile("cp.async.commit_group;");
            asm volatile("cp.async.wait_group 1;");
            __syncthreads();
        }
    }

    if (nc == 1) {
        float inv0 = 1.f / l0, inv1 = 1.f / l1;
        size_t ob0 = (size_t)(b*SEQ + i0)*VP + h*HD;
        size_t ob1 = (size_t)(b*SEQ + i1)*VP + h*HD;
        #pragma unroll
        for (int nt = 0; nt < 8; nt++) {
            int cl = nt*8 + 2*qd;
            *(__half2*)&g_cath[ob0 + cl] = __float22half2_rn(make_float2(o[nt][0]*inv0, o[nt][1]*inv0));
            *(__half2*)&g_cath[ob1 + cl] = __float22half2_rn(make_float2(o[nt][2]*inv1, o[nt][3]*inv1));
        }
    } else {
        const int pb = (bz*32 + qb)*4 + chunk;
        float* po = g_part + (size_t)pb*4096;
        const int r0 = warp*16 + gq;
        const int r1 = r0 + 8;
        #pragma unroll
        for (int nt = 0; nt < 8; nt++) {
            int cl = nt*8 + 2*qd;
            *(float2*)&po[r0*64 + cl] = make_float2(o[nt][0], o[nt][1]);
            *(float2*)&po[r1*64 + cl] = make_float2(o[nt][2], o[nt][3]);
        }
        if (qd == 0) {
            float* ml = g_ml + (size_t)pb*128;
            ml[r0] = m0;  ml[64 + r0] = l0;    // m in log2 domain
            ml[r1] = m1;  ml[64 + r1] = l1;
        }
    }
}

// ---------------- attention combine (qb >= 8) ----------------
__global__ void __launch_bounds__(256) attn_combine_kernel()
{
    const int qb = 8 + blockIdx.x;
    const int bz = blockIdx.y;
    const int h  = bz & 7;
    const int b  = bz >> 3;
    const int nc = qb/CHUNK_TILES + 1;
    const int tid = threadIdx.x;
    const int row = tid >> 2;
    const int dg  = (tid & 3) << 4;

    const int pb0 = (bz*32 + qb)*4;
    float mc[4], lc[4];
    float M = -INFINITY;
    for (int c = 0; c < nc; c++) {
        const float* ml = g_ml + (size_t)(pb0 + c)*128;
        mc[c] = ml[row];
        lc[c] = ml[64 + row];
        M = fmaxf(M, mc[c]);
    }
    float L = 0.f;
    float acc[16];
    #pragma unroll
    for (int i = 0; i < 16; i++) acc[i] = 0.f;
    for (int c = 0; c < nc; c++) {
        float w = exp2f(mc[c] - M);      // log2-domain m
        L += lc[c]*w;
        const float* po = g_part + (size_t)(pb0 + c)*4096 + row*64 + dg;
        #pragma unroll
        for (int i = 0; i < 4; i++) {
            float4 v = *(const float4*)&po[i*4];
            acc[i*4+0] += v.x*w; acc[i*4+1] += v.y*w;
            acc[i*4+2] += v.z*w; acc[i*4+3] += v.w*w;
        }
    }
    float inv = 1.f / L;
    __half* dst = g_cath + (size_t)(b*SEQ + qb*64 + row)*VP + h*HD + dg;
    #pragma unroll
    for (int j = 0; j < 8; j++)
        *(__half2*)&dst[j*2] = __float22half2_rn(make_float2(acc[2*j]*inv, acc[2*j+1]*inv));
}

// ---------------- launch ----------------
extern "C" void kernel_launch(void* const* d_in, const int* in_sizes, int n_in,
                              void* d_out, int out_size)
{
    (void)in_sizes; (void)n_in; (void)out_size;
    const float* x     = (const float*)d_in[0];
    const float* gamma = (const float*)d_in[1];
    const float* beta  = (const float*)d_in[2];
    const float* w_in  = (const float*)d_in[3];
    const float* w_out = (const float*)d_in[4];
    const float* b_out = (const float*)d_in[5];
    float* out = (float*)d_out;

    __half *p_xth, *p_w1t, *p_w2t, *p_cath;
    float *p_part;
    cudaGetSymbolAddress((void**)&p_xth,  g_xth);
    cudaGetSymbolAddress((void**)&p_w1t,  g_w1t);
    cudaGetSymbolAddress((void**)&p_w2t,  g_w2t);
    cudaGetSymbolAddress((void**)&p_cath, g_cath);
    cudaGetSymbolAddress((void**)&p_part, g_part);

    trans_cvt_kernel<<<dim3(HIDDEN/32, QKVP/32), 256>>>(w_in,  p_w1t, HIDDEN, QKVP);
    trans_cvt_kernel<<<dim3(VP/32, HIDDEN/32),   256>>>(w_out, p_w2t, VP, HIDDEN);

    ln_kernel<<<ROWS, 128>>>(x, gamma, beta);
    feat_kernel<<<(ROWS*16 + 255)/256, 256>>>();
    scan_kernel<<<BATCH*64, 256>>>();

    int gemm_smem = 4*ASTG*2;                               // 40960
    cudaFuncSetAttribute(hgemm_kernel<1>, cudaFuncAttributeMaxDynamicSharedMemorySize, gemm_smem);
    cudaFuncSetAttribute(hgemm_kernel<2>, cudaFuncAttributeMaxDynamicSharedMemorySize, gemm_smem);

    dim3 g1(QKVP/128, ROWS/128);     // (28, 32)
    hgemm_kernel<1><<<g1, 256, gemm_smem>>>(p_xth, p_w1t, nullptr, HIDDEN, HIDDEN, HIDDEN, QKVP);

    int attn_smem = 5*QTILE*2;                              // 46080
    cudaFuncSetAttribute(attn_mma_kernel, cudaFuncAttributeMaxDynamicSharedMemorySize, attn_smem);
    attn_mma_kernel<<<dim3(4, SEQ/64, BATCH*HEADS), 128, attn_smem>>>();
    attn_combine_kernel<<<dim3(24, BATCH*HEADS), 256>>>();

    dim3 g2(HIDDEN/128, ROWS/128, KSPLITS);  // (4, 32, 4)
    hgemm_kernel<2><<<g2, 256, gemm_smem>>>(p_cath, p_w2t, p_part, KSPLIT, VP, VP, HIDDEN);
    reduce_kernel<<<(ROWS*HIDDEN/4 + 255)/256, 256>>>(out, b_out);
}

// round 12
// speedup vs baseline: 1.1260x; 1.0177x over previous
#include <cuda_runtime.h>
#include <cuda_fp16.h>
#include <math.h>
#include <stdint.h>

#define BATCH  2
#define SEQ    2048
#define ROWS   (BATCH*SEQ)     // 4096
#define HIDDEN 512
#define QKVP   3584
#define VP     2560
#define HEADS  8
#define HD     64
#define KSPLITS 4
#define KSPLIT  (VP/KSPLITS)   // 640
#define CHUNK_TILES 8
#define LOG2E  1.4426950408889634f

// ---------------- scratch ----------------
__device__ float  g_xn[(size_t)ROWS*HIDDEN];
__device__ __align__(128) __half g_xth [(size_t)ROWS*HIDDEN];
__device__ __align__(128) __half g_projh[(size_t)ROWS*1536];     // q,k,v
__device__ __align__(128) __half g_cath[(size_t)ROWS*VP];
__device__ __align__(128) __half g_w1t[(size_t)QKVP*HIDDEN];     // [N][K]
__device__ __align__(128) __half g_w2t[(size_t)HIDDEN*VP];       // [N][K]
__device__ float  g_part[(size_t)KSPLITS*ROWS*HIDDEN];           // attn partials, then split-K partials
__device__ float  g_ml[(size_t)BATCH*HEADS*32*4*128];

// ---------------- helpers ----------------
__device__ __forceinline__ void mma_f16(float* d, const uint32_t* a, uint32_t b0, uint32_t b1) {
    asm volatile("mma.sync.aligned.m16n8k16.row.col.f32.f16.f16.f32 "
        "{%0,%1,%2,%3}, {%4,%5,%6,%7}, {%8,%9}, {%0,%1,%2,%3};"
        : "+f"(d[0]), "+f"(d[1]), "+f"(d[2]), "+f"(d[3])
        : "r"(a[0]), "r"(a[1]), "r"(a[2]), "r"(a[3]), "r"(b0), "r"(b1));
}
__device__ __forceinline__ void ldsm4(uint32_t* r, uint32_t a) {
    asm volatile("ldmatrix.sync.aligned.m8n8.x4.shared.b16 {%0,%1,%2,%3}, [%4];"
        : "=r"(r[0]), "=r"(r[1]), "=r"(r[2]), "=r"(r[3]) : "r"(a));
}
__device__ __forceinline__ void ldsm4t(uint32_t* r, uint32_t a) {
    asm volatile("ldmatrix.sync.aligned.m8n8.x4.trans.shared.b16 {%0,%1,%2,%3}, [%4];"
        : "=r"(r[0]), "=r"(r[1]), "=r"(r[2]), "=r"(r[3]) : "r"(a));
}
__device__ __forceinline__ void cp16(uint32_t dst, const void* src) {
    asm volatile("cp.async.cg.shared.global [%0], [%1], 16;" :: "r"(dst), "l"(src));
}
// pack two f32 into f16x2 (lo, hi) and exp2 both halves in one MUFU op
__device__ __forceinline__ uint32_t exp2_f16x2(float lo, float hi) {
    uint32_t r;
    asm("{\n\t.reg .b32 t;\n\t"
        "cvt.rn.f16x2.f32 t, %2, %1;\n\t"
        "ex2.approx.f16x2 t, t;\n\t"
        "mov.b32 %0, t;\n\t}"
        : "=r"(r) : "f"(lo), "f"(hi));
    return r;
}

// ---------------- weight transpose + fp16 convert: [K][N] f32 -> [N][K] h ----
__global__ void __launch_bounds__(256) trans_cvt_kernel(
    const float* __restrict__ src, __half* __restrict__ dst, int K, int N)
{
    __shared__ __half t[32][33];
    int k0 = blockIdx.x*32, n0 = blockIdx.y*32;
    int tx = threadIdx.x & 31, ty = threadIdx.x >> 5;
    #pragma unroll
    for (int i = 0; i < 32; i += 8)
        t[ty+i][tx] = __float2half_rn(src[(size_t)(k0+ty+i)*N + n0+tx]);
    __syncthreads();
    #pragma unroll
    for (int i = 0; i < 32; i += 8)
        dst[(size_t)(n0+ty+i)*K + k0+tx] = t[tx][ty+i];
}

// ---------------- LayerNorm (+ fused ident copy), vectorized ----------------
__global__ void __launch_bounds__(128) ln_kernel(const float* __restrict__ x,
                                                 const float* __restrict__ gamma,
                                                 const float* __restrict__ beta)
{
    int row = blockIdx.x;
    int tid = threadIdx.x;
    int c0  = tid*4;
    const float* xr = x + (size_t)row*HIDDEN;
    float4 v = *(const float4*)&xr[c0];
    float s = v.x + v.y + v.z + v.w;
    __shared__ float red[4];
    #pragma unroll
    for (int o = 16; o > 0; o >>= 1) s += __shfl_xor_sync(0xffffffffu, s, o);
    if ((tid & 31) == 0) red[tid >> 5] = s;
    __syncthreads();
    float mu = (red[0]+red[1]+red[2]+red[3]) * (1.f/HIDDEN);
    float vs = (v.x-mu)*(v.x-mu) + (v.y-mu)*(v.y-mu) + (v.z-mu)*(v.z-mu) + (v.w-mu)*(v.w-mu);
    #pragma unroll
    for (int o = 16; o > 0; o >>= 1) vs += __shfl_xor_sync(0xffffffffu, vs, o);
    __syncthreads();
    if ((tid & 31) == 0) red[tid >> 5] = vs;
    __syncthreads();
    float var  = (red[0]+red[1]+red[2]+red[3]) * (1.f/HIDDEN);
    float rstd = rsqrtf(var + 1e-5f);
    float4 g = *(const float4*)&gamma[c0];
    float4 bt = *(const float4*)&beta[c0];
    float4 xn;
    xn.x = (v.x-mu)*rstd*g.x + bt.x;
    xn.y = (v.y-mu)*rstd*g.y + bt.y;
    xn.z = (v.z-mu)*rstd*g.z + bt.z;
    xn.w = (v.w-mu)*rstd*g.w + bt.w;
    *(float4*)&g_xn[(size_t)row*HIDDEN + c0] = xn;
    if (c0 < 320) {
        __half2 h0 = __float22half2_rn(make_float2(xn.x, xn.y));
        __half2 h1 = __float22half2_rn(make_float2(xn.z, xn.w));
        uint2 u = make_uint2(*(uint32_t*)&h0, *(uint32_t*)&h1);
        *(uint2*)&g_xth[(size_t)row*HIDDEN + c0] = u;
    }
}

// ---------------- feature transform: shift channels, 16B stores --------------
__global__ void feat_kernel()
{
    int idx = blockIdx.x*256 + threadIdx.x;
    if (idx >= ROWS*16) return;
    int chunk = idx & 15;
    int row   = idx >> 4;
    int c     = 384 + chunk*8;
    int i     = row & (SEQ-1);
    int sh    = (c < 448) ? 1 : 2;
    float4 v0 = make_float4(0.f,0.f,0.f,0.f), v1 = v0;
    if (i >= sh) {
        const float* src = &g_xn[(size_t)(row-sh)*HIDDEN + c];
        v0 = *(const float4*)src;
        v1 = *(const float4*)(src+4);
    }
    __half2 p0 = __float22half2_rn(make_float2(v0.x, v0.y));
    __half2 p1 = __float22half2_rn(make_float2(v0.z, v0.w));
    __half2 p2 = __float22half2_rn(make_float2(v1.x, v1.y));
    __half2 p3 = __float22half2_rn(make_float2(v1.z, v1.w));
    uint4 u = make_uint4(*(uint32_t*)&p0, *(uint32_t*)&p1, *(uint32_t*)&p2, *(uint32_t*)&p3);
    *(uint4*)&g_xth[(size_t)row*HIDDEN + c] = u;
}

// ---------------- cumlogsumexp scan ----------------
__global__ void __launch_bounds__(256) scan_kernel()
{
    int bc  = blockIdx.x;
    int b   = bc >> 6;
    int ch  = 320 + (bc & 63);
    int tid = threadIdx.x;
    int row0 = b*SEQ + tid*8;
    float y[8];
    #pragma unroll
    for (int i = 0; i < 8; i++) y[i] = 5.f * g_xn[(size_t)(row0+i)*HIDDEN + ch];
    float m = -INFINITY, s = 0.f;
    #pragma unroll
    for (int i = 0; i < 8; i++) {
        float M = fmaxf(m, y[i]);
        s = s*expf(m - M) + expf(y[i] - M);
        m = M;
    }
    __shared__ float sm[256], ss[256];
    sm[tid] = m; ss[tid] = s;
    __syncthreads();
    for (int off = 1; off < 256; off <<= 1) {
        float pm = 0.f, ps = 0.f;
        bool act = (tid >= off);
        if (act) { pm = sm[tid-off]; ps = ss[tid-off]; }
        __syncthreads();
        if (act) {
            float M = fmaxf(pm, m);
            s = ps*expf(pm - M) + s*expf(m - M);
            m = M;
            sm[tid] = m; ss[tid] = s;
        }
        __syncthreads();
    }
    float pm = -INFINITY, ps = 0.f;
    if (tid > 0) { pm = sm[tid-1]; ps = ss[tid-1]; }
    #pragma unroll
    for (int i = 0; i < 8; i++) {
        float M = fmaxf(pm, y[i]);
        ps = ps*expf(pm - M) + expf(y[i] - M);
        pm = M;
        g_xth[(size_t)(row0+i)*HIDDEN + ch] = __float2half_rn((pm + logf(ps)) * 0.2f);
    }
}

// ---------------- fp16 tensor GEMM: 128x128 tile, BK=32, 3-stage pipeline ----
#define AST 40                 // halves per row (80B: 5r mod 8 -> conflict-free ldsm)
#define ASTG (128*AST)
#define NSTG 3
template<int MODE>
__global__ void __launch_bounds__(256, 2) hgemm_kernel(
    const __half* __restrict__ A, const __half* __restrict__ B,
    float* __restrict__ C, int K, int lda, int ldb, int N)
{
    extern __shared__ __half hsm[];
    __half* As = hsm;                    // NSTG x ASTG
    __half* Bs = hsm + NSTG*ASTG;

    if (MODE == 2) {
        const int z = blockIdx.z;
        A += (size_t)z*K;
        B += (size_t)z*K;
        C += (size_t)z*ROWS*N;
    }

    const int tid  = threadIdx.x;
    const int warp = tid >> 5;
    const int lane = tid & 31;
    const int gq = lane >> 2;
    const int qd = lane & 3;
    const int warp_m = (warp & 3) * 32;
    const int warp_n = (warp >> 2) * 64;
    const int m0 = blockIdx.y * 128;
    const int n0 = blockIdx.x * 128;
    const int lrow  = lane & 15;
    const int lcol8 = (lane >> 4) * 8;

    const int a_r  = tid >> 2;
    const int a_c8 = (tid & 3) * 8;

    const uint32_t as_u = (uint32_t)__cvta_generic_to_shared(As);
    const uint32_t bs_u = (uint32_t)__cvta_generic_to_shared(Bs);
    const uint32_t a_dst0 = as_u + (uint32_t)(a_r*AST + a_c8)*2;
    const uint32_t b_dst0 = bs_u + (uint32_t)(a_r*AST + a_c8)*2;

    const __half* Ag0 = A + (size_t)(m0 + a_r)*lda + a_c8;
    const __half* Bg0 = B + (size_t)(n0 + a_r)*ldb + a_c8;

    const int kTiles = K >> 5;

    #pragma unroll
    for (int s = 0; s < NSTG; s++) {
        if (s < kTiles) {
            const __half* Ag = Ag0 + s*32;
            const __half* Bg = Bg0 + s*32;
            #pragma unroll
            for (int i = 0; i < 2; i++) {
                cp16(a_dst0 + (uint32_t)(s*ASTG + i*64*AST)*2, Ag + (size_t)i*64*lda);
                cp16(b_dst0 + (uint32_t)(s*ASTG + i*64*AST)*2, Bg + (size_t)i*64*ldb);
            }
        }
        asm volatile("cp.async.commit_group;");
    }
    asm volatile("cp.async.wait_group 2;");
    __syncthreads();

    float acc[2][8][4];
    #pragma unroll
    for (int mt = 0; mt < 2; mt++)
        #pragma unroll
        for (int nt = 0; nt < 8; nt++)
            #pragma unroll
            for (int i = 0; i < 4; i++) acc[mt][nt][i] = 0.f;

    int stage = 0;
    for (int t = 0; t < kTiles; t++) {
        const uint32_t asb = as_u + (uint32_t)(stage*ASTG)*2;
        const uint32_t bsb = bs_u + (uint32_t)(stage*ASTG)*2;
        #pragma unroll
        for (int kk = 0; kk < 2; kk++) {
            uint32_t af[2][4];
            #pragma unroll
            for (int mt = 0; mt < 2; mt++)
                ldsm4(af[mt], asb + (uint32_t)((warp_m + mt*16 + lrow)*AST + kk*16 + lcol8)*2);
            #pragma unroll
            for (int p = 0; p < 4; p++) {
                uint32_t bf[4];
                ldsm4(bf, bsb + (uint32_t)((warp_n + p*16 + lrow)*AST + kk*16 + lcol8)*2);
                mma_f16(acc[0][2*p],   af[0], bf[0], bf[2]);
                mma_f16(acc[0][2*p+1], af[0], bf[1], bf[3]);
                mma_f16(acc[1][2*p],   af[1], bf[0], bf[2]);
                mma_f16(acc[1][2*p+1], af[1], bf[1], bf[3]);
            }
        }
        if (t + 1 < kTiles) {
            __syncthreads();                      // done reading this stage
            if (t + NSTG < kTiles) {              // refill freed stage with tile t+NSTG
                const __half* Ag = Ag0 + (t+NSTG)*32;
                const __half* Bg = Bg0 + (t+NSTG)*32;
                #pragma unroll
                for (int i = 0; i < 2; i++) {
                    cp16(a_dst0 + (uint32_t)(stage*ASTG + i*64*AST)*2, Ag + (size_t)i*64*lda);
                    cp16(b_dst0 + (uint32_t)(stage*ASTG + i*64*AST)*2, Bg + (size_t)i*64*ldb);
                }
            }
            asm volatile("cp.async.commit_group;");
            asm volatile("cp.async.wait_group 2;");   // tile t+1 landed
            __syncthreads();
        }
        stage = (stage + 1 == NSTG) ? 0 : stage + 1;
    }

    #pragma unroll
    for (int mt = 0; mt < 2; mt++) {
        const int r0 = m0 + warp_m + mt*16 + gq;
        #pragma unroll
        for (int nt = 0; nt < 8; nt++) {
            const int c = n0 + warp_n + nt*8 + 2*qd;
            if (MODE == 1) {
                if (c >= 1536) {
                    #pragma unroll
                    for (int hh = 0; hh < 2; hh++) {
                        int rr = r0 + hh*8;
                        float v0 = acc[mt][nt][hh*2+0], v1 = acc[mt][nt][hh*2+1];
                        float gl0 = 0.5f*v0*(1.f + erff(v0*0.70710678118654752f));
                        float gl1 = 0.5f*v1*(1.f + erff(v1*0.70710678118654752f));
                        *(__half2*)&g_cath[(size_t)rr*VP + (c - 1024)] =
                            __float22half2_rn(make_float2(gl0, gl1));
                    }
                } else {
                    #pragma unroll
                    for (int hh = 0; hh < 2; hh++) {
                        int rr = r0 + hh*8;
                        *(__half2*)&g_projh[(size_t)rr*1536 + c] =
                            __float22half2_rn(make_float2(acc[mt][nt][hh*2+0], acc[mt][nt][hh*2+1]));
                    }
                }
            } else {
                *(float2*)&C[(size_t)r0    *N + c] = make_float2(acc[mt][nt][0], acc[mt][nt][1]);
                *(float2*)&C[(size_t)(r0+8)*N + c] = make_float2(acc[mt][nt][2], acc[mt][nt][3]);
            }
        }
    }
}

// ---------------- split-K reduce + bias ----------------
__global__ void reduce_kernel(float* __restrict__ out, const float* __restrict__ bias)
{
    int i = blockIdx.x*256 + threadIdx.x;
    if (i >= ROWS*HIDDEN/4) return;
    size_t off = (size_t)i*4;
    const size_t stride = (size_t)ROWS*HIDDEN;
    float4 a = *(const float4*)&g_part[off];
    float4 b = *(const float4*)&g_part[off + stride];
    float4 c = *(const float4*)&g_part[off + 2*stride];
    float4 d = *(const float4*)&g_part[off + 3*stride];
    int col = (int)(off & (HIDDEN-1));
    float4 bb = *(const float4*)&bias[col];
    float4 r;
    r.x = a.x + b.x + c.x + d.x + bb.x;
    r.y = a.y + b.y + c.y + d.y + bb.y;
    r.z = a.z + b.z + c.z + d.z + bb.z;
    r.w = a.w + b.w + c.w + d.w + bb.w;
    *(float4*)&out[off] = r;
}

// ---------------- flash attention: fp16 mma, split-K, f16x2 exp2 softmax ------
#define QST 72
#define QTILE (64*QST)
__global__ void __launch_bounds__(128, 4) attn_mma_kernel()
{
    const int qb     = blockIdx.y;
    const int ntiles = qb + 1;
    const int chunk  = blockIdx.x;
    const int start  = chunk*CHUNK_TILES;
    if (start >= ntiles) return;
    const int end    = min(start + CHUNK_TILES, ntiles);
    const int nc     = (ntiles + CHUNK_TILES - 1) / CHUNK_TILES;
    const int nt_loc = end - start;

    extern __shared__ __half asm_[];
    const int bz = blockIdx.z;
    const int h  = bz & 7;
    const int b  = bz >> 3;
    const int q0 = qb*64;
    const int tid  = threadIdx.x;
    const int warp = tid >> 5;
    const int lane = tid & 31;
    const int gq = lane >> 2;
    const int qd = lane & 3;
    const int lrow  = lane & 15;
    const int lcol8 = (lane >> 4) * 8;
    const int vrow  = (lane & 7) + ((lane >> 3) & 1) * 8;

    const float scale2 = 0.125f * LOG2E;
    const float slope2 = exp2f(-(float)(h+1)) * LOG2E;

    const uint32_t q_u = (uint32_t)__cvta_generic_to_shared(asm_);
    const uint32_t k_u[2] = { q_u + (uint32_t)QTILE*2, q_u + (uint32_t)(3*QTILE)*2 };
    const uint32_t v_u[2] = { q_u + (uint32_t)(2*QTILE)*2, q_u + (uint32_t)(4*QTILE)*2 };

    const int cr  = tid >> 3;
    const int cc8 = (tid & 7) * 8;

    {
        const __half* qb_ = g_projh + (size_t)(b*SEQ + q0 + cr)*1536 + h*HD + cc8;
        #pragma unroll
        for (int i = 0; i < 4; i++)
            cp16(q_u + (uint32_t)((cr + i*16)*QST + cc8)*2, qb_ + (size_t)i*16*1536);
        const __half* kv = g_projh + (size_t)(b*SEQ + start*64 + cr)*1536 + h*HD + cc8;
        #pragma unroll
        for (int i = 0; i < 4; i++) {
            cp16(k_u[0] + (uint32_t)((cr + i*16)*QST + cc8)*2, kv + (size_t)i*16*1536 + 512);
            cp16(v_u[0] + (uint32_t)((cr + i*16)*QST + cc8)*2, kv + (size_t)i*16*1536 + 1024);
        }
        asm volatile("cp.async.commit_group;");
    }
    if (nt_loc > 1) {
        const __half* kv = g_projh + (size_t)(b*SEQ + (start+1)*64 + cr)*1536 + h*HD + cc8;
        #pragma unroll
        for (int i = 0; i < 4; i++) {
            cp16(k_u[1] + (uint32_t)((cr + i*16)*QST + cc8)*2, kv + (size_t)i*16*1536 + 512);
            cp16(v_u[1] + (uint32_t)((cr + i*16)*QST + cc8)*2, kv + (size_t)i*16*1536 + 1024);
        }
    }
    asm volatile("cp.async.commit_group;");
    asm volatile("cp.async.wait_group 1;");
    __syncthreads();

    uint32_t qf[4][4];
    #pragma unroll
    for (int kt = 0; kt < 4; kt++)
        ldsm4(qf[kt], q_u + (uint32_t)((warp*16 + lrow)*QST + kt*16 + lcol8)*2);

    float o[8][4];
    #pragma unroll
    for (int t = 0; t < 8; t++) { o[t][0]=0.f; o[t][1]=0.f; o[t][2]=0.f; o[t][3]=0.f; }
    float m0 = -INFINITY, m1 = -INFINITY, l0 = 0.f, l1 = 0.f;
    const int i0 = q0 + warp*16 + gq;
    const int i1 = i0 + 8;

    for (int lt = 0; lt < nt_loc; lt++) {
        const int j0 = (start + lt)*64;
        const int st = lt & 1;

        float s[8][4];
        #pragma unroll
        for (int t = 0; t < 8; t++) { s[t][0]=0.f; s[t][1]=0.f; s[t][2]=0.f; s[t][3]=0.f; }
        #pragma unroll
        for (int kt = 0; kt < 4; kt++) {
            #pragma unroll
            for (int p = 0; p < 4; p++) {
                uint32_t bf[4];
                ldsm4(bf, k_u[st] + (uint32_t)((p*16 + lrow)*QST + kt*16 + lcol8)*2);
                mma_f16(s[2*p],   qf[kt], bf[0], bf[2]);
                mma_f16(s[2*p+1], qf[kt], bf[1], bf[3]);
            }
        }

        float rm0 = -INFINITY, rm1 = -INFINITY;
        #pragma unroll
        for (int nt = 0; nt < 8; nt++) {
            int j = j0 + nt*8 + 2*qd;
            s[nt][0] = (j   <= i0) ? fmaf(s[nt][0], scale2, slope2*(float)j    ) : -1e30f;
            s[nt][1] = (j+1 <= i0) ? fmaf(s[nt][1], scale2, slope2*(float)(j+1)) : -1e30f;
            s[nt][2] = (j   <= i1) ? fmaf(s[nt][2], scale2, slope2*(float)j    ) : -1e30f;
            s[nt][3] = (j+1 <= i1) ? fmaf(s[nt][3], scale2, slope2*(float)(j+1)) : -1e30f;
            rm0 = fmaxf(rm0, fmaxf(s[nt][0], s[nt][1]));
            rm1 = fmaxf(rm1, fmaxf(s[nt][2], s[nt][3]));
        }
        rm0 = fmaxf(rm0, __shfl_xor_sync(0xffffffffu, rm0, 1));
        rm0 = fmaxf(rm0, __shfl_xor_sync(0xffffffffu, rm0, 2));
        rm1 = fmaxf(rm1, __shfl_xor_sync(0xffffffffu, rm1, 1));
        rm1 = fmaxf(rm1, __shfl_xor_sync(0xffffffffu, rm1, 2));
        float nm0 = fmaxf(m0, rm0), nm1 = fmaxf(m1, rm1);
        float c0 = exp2f(m0 - nm0), c1 = exp2f(m1 - nm1);
        m0 = nm0; m1 = nm1;

        // p in fp16 directly (one MUFU per pair); l summed from the same f16 values
        uint32_t ph[8][2];
        float ps0 = 0.f, ps1 = 0.f;
        #pragma unroll
        for (int nt = 0; nt < 8; nt++) {
            ph[nt][0] = exp2_f16x2(s[nt][0] - nm0, s[nt][1] - nm0);
            ph[nt][1] = exp2_f16x2(s[nt][2] - nm1, s[nt][3] - nm1);
            float2 f0 = __half22float2(*(__half2*)&ph[nt][0]);
            float2 f1 = __half22float2(*(__half2*)&ph[nt][1]);
            ps0 += f0.x + f0.y;
            ps1 += f1.x + f1.y;
            o[nt][0] *= c0; o[nt][1] *= c0; o[nt][2] *= c1; o[nt][3] *= c1;
        }
        ps0 += __shfl_xor_sync(0xffffffffu, ps0, 1);
        ps0 += __shfl_xor_sync(0xffffffffu, ps0, 2);
        ps1 += __shfl_xor_sync(0xffffffffu, ps1, 1);
        ps1 += __shfl_xor_sync(0xffffffffu, ps1, 2);
        l0 = l0*c0 + ps0;
        l1 = l1*c1 + ps1;

        #pragma unroll
        for (int c = 0; c < 4; c++) {
            uint32_t pa[4];
            pa[0] = ph[2*c][0];
            pa[1] = ph[2*c][1];
            pa[2] = ph[2*c+1][0];
            pa[3] = ph[2*c+1][1];
            #pragma unroll
            for (int p = 0; p < 4; p++) {
                uint32_t bf[4];
                ldsm4t(bf, v_u[st] + (uint32_t)((c*16 + vrow)*QST + p*16 + lcol8)*2);
                mma_f16(o[2*p],   pa, bf[0], bf[1]);
                mma_f16(o[2*p+1], pa, bf[2], bf[3]);
            }
        }
        __syncthreads();

        if (lt + 1 < nt_loc) {
            if (lt + 2 < nt_loc) {
                const int jn = (start + lt + 2)*64;
                const __half* kv = g_projh + (size_t)(b*SEQ + jn + cr)*1536 + h*HD + cc8;
                #pragma unroll
                for (int i = 0; i < 4; i++) {
                    cp16(k_u[st] + (uint32_t)((cr + i*16)*QST + cc8)*2, kv + (size_t)i*16*1536 + 512);
                    cp16(v_u[st] + (uint32_t)((cr + i*16)*QST + cc8)*2, kv + (size_t)i*16*1536 + 1024);
                }
            }
            asm volatile("cp.async.commit_group;");
            asm volatile("cp.async.wait_group 1;");
            __syncthreads();
        }
    }

    if (nc == 1) {
        float inv0 = 1.f / l0, inv1 = 1.f / l1;
        size_t ob0 = (size_t)(b*SEQ + i0)*VP + h*HD;
        size_t ob1 = (size_t)(b*SEQ + i1)*VP + h*HD;
        #pragma unroll
        for (int nt = 0; nt < 8; nt++) {
            int cl = nt*8 + 2*qd;
            *(__half2*)&g_cath[ob0 + cl] = __float22half2_rn(make_float2(o[nt][0]*inv0, o[nt][1]*inv0));
            *(__half2*)&g_cath[ob1 + cl] = __float22half2_rn(make_float2(o[nt][2]*inv1, o[nt][3]*inv1));
        }
    } else {
        const int pb = (bz*32 + qb)*4 + chunk;
        float* po = g_part + (size_t)pb*4096;
        const int r0 = warp*16 + gq;
        const int r1 = r0 + 8;
        #pragma unroll
        for (int nt = 0; nt < 8; nt++) {
            int cl = nt*8 + 2*qd;
            *(float2*)&po[r0*64 + cl] = make_float2(o[nt][0], o[nt][1]);
            *(float2*)&po[r1*64 + cl] = make_float2(o[nt][2], o[nt][3]);
        }
        if (qd == 0) {
            float* ml = g_ml + (size_t)pb*128;
            ml[r0] = m0;  ml[64 + r0] = l0;    // m in log2 domain
            ml[r1] = m1;  ml[64 + r1] = l1;
        }
    }
}

// ---------------- attention combine (qb >= 8) ----------------
__global__ void __launch_bounds__(256) attn_combine_kernel()
{
    const int qb = 8 + blockIdx.x;
    const int bz = blockIdx.y;
    const int h  = bz & 7;
    const int b  = bz >> 3;
    const int nc = qb/CHUNK_TILES + 1;
    const int tid = threadIdx.x;
    const int row = tid >> 2;
    const int dg  = (tid & 3) << 4;

    const int pb0 = (bz*32 + qb)*4;
    float mc[4], lc[4];
    float M = -INFINITY;
    for (int c = 0; c < nc; c++) {
        const float* ml = g_ml + (size_t)(pb0 + c)*128;
        mc[c] = ml[row];
        lc[c] = ml[64 + row];
        M = fmaxf(M, mc[c]);
    }
    float L = 0.f;
    float acc[16];
    #pragma unroll
    for (int i = 0; i < 16; i++) acc[i] = 0.f;
    for (int c = 0; c < nc; c++) {
        float w = exp2f(mc[c] - M);      // log2-domain m
        L += lc[c]*w;
        const float* po = g_part + (size_t)(pb0 + c)*4096 + row*64 + dg;
        #pragma unroll
        for (int i = 0; i < 4; i++) {
            float4 v = *(const float4*)&po[i*4];
            acc[i*4+0] += v.x*w; acc[i*4+1] += v.y*w;
            acc[i*4+2] += v.z*w; acc[i*4+3] += v.w*w;
        }
    }
    float inv = 1.f / L;
    __half* dst = g_cath + (size_t)(b*SEQ + qb*64 + row)*VP + h*HD + dg;
    #pragma unroll
    for (int j = 0; j < 8; j++)
        *(__half2*)&dst[j*2] = __float22half2_rn(make_float2(acc[2*j]*inv, acc[2*j+1]*inv));
}

// ---------------- launch ----------------
extern "C" void kernel_launch(void* const* d_in, const int* in_sizes, int n_in,
                              void* d_out, int out_size)
{
    (void)in_sizes; (void)n_in; (void)out_size;
    const float* x     = (const float*)d_in[0];
    const float* gamma = (const float*)d_in[1];
    const float* beta  = (const float*)d_in[2];
    const float* w_in  = (const float*)d_in[3];
    const float* w_out = (const float*)d_in[4];
    const float* b_out = (const float*)d_in[5];
    float* out = (float*)d_out;

    __half *p_xth, *p_w1t, *p_w2t, *p_cath;
    float *p_part;
    cudaGetSymbolAddress((void**)&p_xth,  g_xth);
    cudaGetSymbolAddress((void**)&p_w1t,  g_w1t);
    cudaGetSymbolAddress((void**)&p_w2t,  g_w2t);
    cudaGetSymbolAddress((void**)&p_cath, g_cath);
    cudaGetSymbolAddress((void**)&p_part, g_part);

    trans_cvt_kernel<<<dim3(HIDDEN/32, QKVP/32), 256>>>(w_in,  p_w1t, HIDDEN, QKVP);
    trans_cvt_kernel<<<dim3(VP/32, HIDDEN/32),   256>>>(w_out, p_w2t, VP, HIDDEN);

    ln_kernel<<<ROWS, 128>>>(x, gamma, beta);
    feat_kernel<<<(ROWS*16 + 255)/256, 256>>>();
    scan_kernel<<<BATCH*64, 256>>>();

    int gemm_smem = 2*NSTG*ASTG*2;                          // 61440
    cudaFuncSetAttribute(hgemm_kernel<1>, cudaFuncAttributeMaxDynamicSharedMemorySize, gemm_smem);
    cudaFuncSetAttribute(hgemm_kernel<2>, cudaFuncAttributeMaxDynamicSharedMemorySize, gemm_smem);

    dim3 g1(QKVP/128, ROWS/128);     // (28, 32)
    hgemm_kernel<1><<<g1, 256, gemm_smem>>>(p_xth, p_w1t, nullptr, HIDDEN, HIDDEN, HIDDEN, QKVP);

    int attn_smem = 5*QTILE*2;                              // 46080
    cudaFuncSetAttribute(attn_mma_kernel, cudaFuncAttributeMaxDynamicSharedMemorySize, attn_smem);
    attn_mma_kernel<<<dim3(4, SEQ/64, BATCH*HEADS), 128, attn_smem>>>();
    attn_combine_kernel<<<dim3(24, BATCH*HEADS), 256>>>();

    dim3 g2(HIDDEN/128, ROWS/128, KSPLITS);  // (4, 32, 4)
    hgemm_kernel<2><<<g2, 256, gemm_smem>>>(p_cath, p_w2t, p_part, KSPLIT, VP, VP, HIDDEN);
    reduce_kernel<<<(ROWS*HIDDEN/4 + 255)/256, 256>>>(out, b_out);
}

// round 15
// speedup vs baseline: 1.1890x; 1.0560x over previous
#include <cuda_runtime.h>
#include <cuda_fp16.h>
#include <math.h>
#include <stdint.h>

#define BATCH  2
#define SEQ    2048
#define ROWS   (BATCH*SEQ)     // 4096
#define HIDDEN 512
#define QKVP   3584
#define VP     2560
#define HEADS  8
#define HD     64
#define KSPLITS 4
#define KSPLIT  (VP/KSPLITS)   // 640
#define CHUNK_TILES 8
#define LOG2E  1.4426950408889634f

// ---------------- scratch ----------------
__device__ float  g_xn[(size_t)ROWS*HIDDEN];
__device__ __align__(128) __half g_xth [(size_t)ROWS*HIDDEN];
__device__ __align__(128) __half g_projh[(size_t)ROWS*1536];     // q,k,v
__device__ __align__(128) __half g_cath[(size_t)ROWS*VP];
__device__ __align__(128) __half g_w1t[(size_t)QKVP*HIDDEN];     // [N][K]
__device__ __align__(128) __half g_w2t[(size_t)HIDDEN*VP];       // [N][K]
__device__ float  g_part[(size_t)KSPLITS*ROWS*HIDDEN];           // attn partials, then split-K partials
__device__ float  g_ml[(size_t)BATCH*HEADS*32*4*128];

// ---------------- helpers ----------------
__device__ __forceinline__ void mma_f16(float* d, const uint32_t* a, uint32_t b0, uint32_t b1) {
    asm volatile("mma.sync.aligned.m16n8k16.row.col.f32.f16.f16.f32 "
        "{%0,%1,%2,%3}, {%4,%5,%6,%7}, {%8,%9}, {%0,%1,%2,%3};"
        : "+f"(d[0]), "+f"(d[1]), "+f"(d[2]), "+f"(d[3])
        : "r"(a[0]), "r"(a[1]), "r"(a[2]), "r"(a[3]), "r"(b0), "r"(b1));
}
__device__ __forceinline__ void ldsm4(uint32_t* r, uint32_t a) {
    asm volatile("ldmatrix.sync.aligned.m8n8.x4.shared.b16 {%0,%1,%2,%3}, [%4];"
        : "=r"(r[0]), "=r"(r[1]), "=r"(r[2]), "=r"(r[3]) : "r"(a));
}
__device__ __forceinline__ void ldsm4t(uint32_t* r, uint32_t a) {
    asm volatile("ldmatrix.sync.aligned.m8n8.x4.trans.shared.b16 {%0,%1,%2,%3}, [%4];"
        : "=r"(r[0]), "=r"(r[1]), "=r"(r[2]), "=r"(r[3]) : "r"(a));
}
__device__ __forceinline__ void cp16(uint32_t dst, const void* src) {
    asm volatile("cp.async.cg.shared.global [%0], [%1], 16;" :: "r"(dst), "l"(src));
}
__device__ __forceinline__ uint32_t exp2_f16x2(float lo, float hi) {
    uint32_t r;
    asm("{\n\t.reg .b32 t;\n\t"
        "cvt.rn.f16x2.f32 t, %2, %1;\n\t"
        "ex2.approx.f16x2 t, t;\n\t"
        "mov.b32 %0, t;\n\t}"
        : "=r"(r) : "f"(lo), "f"(hi));
    return r;
}

// ---------------- merged weight transpose+cvt: both weights, one launch ------
__device__ __forceinline__ void trans_tile(const float* __restrict__ src,
                                           __half* __restrict__ dst,
                                           int K, int N, int k0, int n0)
{
    __shared__ __half t[32][33];
    int tx = threadIdx.x & 31, ty = threadIdx.x >> 5;
    #pragma unroll
    for (int i = 0; i < 32; i += 8)
        t[ty+i][tx] = __float2half_rn(src[(size_t)(k0+ty+i)*N + n0+tx]);
    __syncthreads();
    #pragma unroll
    for (int i = 0; i < 32; i += 8)
        dst[(size_t)(n0+ty+i)*K + k0+tx] = t[tx][ty+i];
}
#define W1_BLOCKS ((HIDDEN/32)*(QKVP/32))   // 16*112 = 1792
#define W2_BLOCKS ((VP/32)*(HIDDEN/32))     // 80*16  = 1280
__global__ void __launch_bounds__(256) weights_cvt_kernel(
    const float* __restrict__ w_in, const float* __restrict__ w_out,
    __half* __restrict__ w1t, __half* __restrict__ w2t)
{
    int bid = blockIdx.x;
    if (bid < W1_BLOCKS) {
        int bx = bid & 15, by = bid >> 4;               // 16 x 112
        trans_tile(w_in, w1t, HIDDEN, QKVP, bx*32, by*32);
    } else {
        int b2 = bid - W1_BLOCKS;
        int bx = b2 % 80, by = b2 / 80;                 // 80 x 16
        trans_tile(w_out, w2t, VP, HIDDEN, bx*32, by*32);
    }
}

// ---------------- LayerNorm (+ fused ident copy), vectorized ----------------
__global__ void __launch_bounds__(128) ln_kernel(const float* __restrict__ x,
                                                 const float* __restrict__ gamma,
                                                 const float* __restrict__ beta)
{
    int row = blockIdx.x;
    int tid = threadIdx.x;
    int c0  = tid*4;
    const float* xr = x + (size_t)row*HIDDEN;
    float4 v = *(const float4*)&xr[c0];
    float s = v.x + v.y + v.z + v.w;
    __shared__ float red[4];
    #pragma unroll
    for (int o = 16; o > 0; o >>= 1) s += __shfl_xor_sync(0xffffffffu, s, o);
    if ((tid & 31) == 0) red[tid >> 5] = s;
    __syncthreads();
    float mu = (red[0]+red[1]+red[2]+red[3]) * (1.f/HIDDEN);
    float vs = (v.x-mu)*(v.x-mu) + (v.y-mu)*(v.y-mu) + (v.z-mu)*(v.z-mu) + (v.w-mu)*(v.w-mu);
    #pragma unroll
    for (int o = 16; o > 0; o >>= 1) vs += __shfl_xor_sync(0xffffffffu, vs, o);
    __syncthreads();
    if ((tid & 31) == 0) red[tid >> 5] = vs;
    __syncthreads();
    float var  = (red[0]+red[1]+red[2]+red[3]) * (1.f/HIDDEN);
    float rstd = rsqrtf(var + 1e-5f);
    float4 g = *(const float4*)&gamma[c0];
    float4 bt = *(const float4*)&beta[c0];
    float4 xn;
    xn.x = (v.x-mu)*rstd*g.x + bt.x;
    xn.y = (v.y-mu)*rstd*g.y + bt.y;
    xn.z = (v.z-mu)*rstd*g.z + bt.z;
    xn.w = (v.w-mu)*rstd*g.w + bt.w;
    *(float4*)&g_xn[(size_t)row*HIDDEN + c0] = xn;
    if (c0 < 320) {
        __half2 h0 = __float22half2_rn(make_float2(xn.x, xn.y));
        __half2 h1 = __float22half2_rn(make_float2(xn.z, xn.w));
        uint2 u = make_uint2(*(uint32_t*)&h0, *(uint32_t*)&h1);
        *(uint2*)&g_xth[(size_t)row*HIDDEN + c0] = u;
    }
}

// ---------------- merged feat (shift) + cumlogsumexp scan, one launch --------
__device__ void scan_body(int bc)
{
    int b   = bc >> 6;
    int ch  = 320 + (bc & 63);
    int tid = threadIdx.x;
    int row0 = b*SEQ + tid*8;
    float y[8];
    #pragma unroll
    for (int i = 0; i < 8; i++) y[i] = 5.f * g_xn[(size_t)(row0+i)*HIDDEN + ch];
    float m = -INFINITY, s = 0.f;
    #pragma unroll
    for (int i = 0; i < 8; i++) {
        float M = fmaxf(m, y[i]);
        s = s*expf(m - M) + expf(y[i] - M);
        m = M;
    }
    __shared__ float sm[256], ss[256];
    sm[tid] = m; ss[tid] = s;
    __syncthreads();
    for (int off = 1; off < 256; off <<= 1) {
        float pm = 0.f, ps = 0.f;
        bool act = (tid >= off);
        if (act) { pm = sm[tid-off]; ps = ss[tid-off]; }
        __syncthreads();
        if (act) {
            float M = fmaxf(pm, m);
            s = ps*expf(pm - M) + s*expf(m - M);
            m = M;
            sm[tid] = m; ss[tid] = s;
        }
        __syncthreads();
    }
    float pm = -INFINITY, ps = 0.f;
    if (tid > 0) { pm = sm[tid-1]; ps = ss[tid-1]; }
    #pragma unroll
    for (int i = 0; i < 8; i++) {
        float M = fmaxf(pm, y[i]);
        ps = ps*expf(pm - M) + expf(y[i] - M);
        pm = M;
        g_xth[(size_t)(row0+i)*HIDDEN + ch] = __float2half_rn((pm + logf(ps)) * 0.2f);
    }
}
__device__ void feat_body(int fb)
{
    int idx = fb*256 + threadIdx.x;
    if (idx >= ROWS*16) return;
    int chunk = idx & 15;
    int row   = idx >> 4;
    int c     = 384 + chunk*8;
    int i     = row & (SEQ-1);
    int sh    = (c < 448) ? 1 : 2;
    float4 v0 = make_float4(0.f,0.f,0.f,0.f), v1 = v0;
    if (i >= sh) {
        const float* src = &g_xn[(size_t)(row-sh)*HIDDEN + c];
        v0 = *(const float4*)src;
        v1 = *(const float4*)(src+4);
    }
    __half2 p0 = __float22half2_rn(make_float2(v0.x, v0.y));
    __half2 p1 = __float22half2_rn(make_float2(v0.z, v0.w));
    __half2 p2 = __float22half2_rn(make_float2(v1.x, v1.y));
    __half2 p3 = __float22half2_rn(make_float2(v1.z, v1.w));
    uint4 u = make_uint4(*(uint32_t*)&p0, *(uint32_t*)&p1, *(uint32_t*)&p2, *(uint32_t*)&p3);
    *(uint4*)&g_xth[(size_t)row*HIDDEN + c] = u;
}
__global__ void __launch_bounds__(256) featscan_kernel()
{
    if (blockIdx.x < BATCH*64) scan_body(blockIdx.x);
    else                       feat_body(blockIdx.x - BATCH*64);
}

// ---------------- fp16 tensor GEMM: BK=32, 3-stage, single-sync mainloop -----
#define AST 40                 // halves per row (80B: 5r mod 8 -> conflict-free ldsm)
#define ASTG (128*AST)
#define NSTG 3
template<int MODE>
__global__ void __launch_bounds__(256, 2) hgemm_kernel(
    const __half* __restrict__ A, const __half* __restrict__ B,
    float* __restrict__ C, int K, int lda, int ldb, int N)
{
    extern __shared__ __half hsm[];
    __half* As = hsm;                    // NSTG x ASTG
    __half* Bs = hsm + NSTG*ASTG;

    if (MODE == 2) {
        const int z = blockIdx.z;
        A += (size_t)z*K;
        B += (size_t)z*K;
        C += (size_t)z*ROWS*N;
    }

    const int tid  = threadIdx.x;
    const int warp = tid >> 5;
    const int lane = tid & 31;
    const int gq = lane >> 2;
    const int qd = lane & 3;
    const int warp_m = (warp & 3) * 32;
    const int warp_n = (warp >> 2) * 64;
    const int m0 = blockIdx.y * 128;
    const int n0 = blockIdx.x * 128;
    const int lrow  = lane & 15;
    const int lcol8 = (lane >> 4) * 8;

    const int a_r  = tid >> 2;
    const int a_c8 = (tid & 3) * 8;

    const uint32_t as_u = (uint32_t)__cvta_generic_to_shared(As);
    const uint32_t bs_u = (uint32_t)__cvta_generic_to_shared(Bs);
    const uint32_t a_dst0 = as_u + (uint32_t)(a_r*AST + a_c8)*2;
    const uint32_t b_dst0 = bs_u + (uint32_t)(a_r*AST + a_c8)*2;

    const __half* Ag0 = A + (size_t)(m0 + a_r)*lda + a_c8;
    const __half* Bg0 = B + (size_t)(n0 + a_r)*ldb + a_c8;

    const int kTiles = K >> 5;

    #pragma unroll
    for (int s = 0; s < NSTG; s++) {
        if (s < kTiles) {
            const __half* Ag = Ag0 + s*32;
            const __half* Bg = Bg0 + s*32;
            #pragma unroll
            for (int i = 0; i < 2; i++) {
                cp16(a_dst0 + (uint32_t)(s*ASTG + i*64*AST)*2, Ag + (size_t)i*64*lda);
                cp16(b_dst0 + (uint32_t)(s*ASTG + i*64*AST)*2, Bg + (size_t)i*64*ldb);
            }
        }
        asm volatile("cp.async.commit_group;");
    }
    asm volatile("cp.async.wait_group %0;" :: "n"(NSTG-1));
    __syncthreads();

    float acc[2][8][4];
    #pragma unroll
    for (int mt = 0; mt < 2; mt++)
        #pragma unroll
        for (int nt = 0; nt < 8; nt++)
            #pragma unroll
            for (int i = 0; i < 4; i++) acc[mt][nt][i] = 0.f;

    int stage = 0;
    for (int t = 0; t < kTiles; t++) {
        const uint32_t asb = as_u + (uint32_t)(stage*ASTG)*2;
        const uint32_t bsb = bs_u + (uint32_t)(stage*ASTG)*2;
        #pragma unroll
        for (int kk = 0; kk < 2; kk++) {
            uint32_t af[2][4];
            #pragma unroll
            for (int mt = 0; mt < 2; mt++)
                ldsm4(af[mt], asb + (uint32_t)((warp_m + mt*16 + lrow)*AST + kk*16 + lcol8)*2);
            #pragma unroll
            for (int p = 0; p < 4; p++) {
                uint32_t bf[4];
                ldsm4(bf, bsb + (uint32_t)((warp_n + p*16 + lrow)*AST + kk*16 + lcol8)*2);
                mma_f16(acc[0][2*p],   af[0], bf[0], bf[2]);
                mma_f16(acc[0][2*p+1], af[0], bf[1], bf[3]);
                mma_f16(acc[1][2*p],   af[1], bf[0], bf[2]);
                mma_f16(acc[1][2*p+1], af[1], bf[1], bf[3]);
            }
        }
        // single barrier per iteration: all warps done reading this stage
        __syncthreads();
        if (t + NSTG < kTiles) {           // refill the just-freed stage
            const __half* Ag = Ag0 + (t+NSTG)*32;
            const __half* Bg = Bg0 + (t+NSTG)*32;
            #pragma unroll
            for (int i = 0; i < 2; i++) {
                cp16(a_dst0 + (uint32_t)(stage*ASTG + i*64*AST)*2, Ag + (size_t)i*64*lda);
                cp16(b_dst0 + (uint32_t)(stage*ASTG + i*64*AST)*2, Bg + (size_t)i*64*ldb);
            }
        }
        asm volatile("cp.async.commit_group;");
        asm volatile("cp.async.wait_group %0;" :: "n"(NSTG-1));   // tile t+1 landed
        stage = (stage + 1 == NSTG) ? 0 : stage + 1;
    }

    #pragma unroll
    for (int mt = 0; mt < 2; mt++) {
        const int r0 = m0 + warp_m + mt*16 + gq;
        #pragma unroll
        for (int nt = 0; nt < 8; nt++) {
            const int c = n0 + warp_n + nt*8 + 2*qd;
            if (MODE == 1) {
                if (c >= 1536) {
                    #pragma unroll
                    for (int hh = 0; hh < 2; hh++) {
                        int rr = r0 + hh*8;
                        float v0 = acc[mt][nt][hh*2+0], v1 = acc[mt][nt][hh*2+1];
                        float gl0 = 0.5f*v0*(1.f + erff(v0*0.70710678118654752f));
                        float gl1 = 0.5f*v1*(1.f + erff(v1*0.70710678118654752f));
                        *(__half2*)&g_cath[(size_t)rr*VP + (c - 1024)] =
                            __float22half2_rn(make_float2(gl0, gl1));
                    }
                } else {
                    #pragma unroll
                    for (int hh = 0; hh < 2; hh++) {
                        int rr = r0 + hh*8;
                        *(__half2*)&g_projh[(size_t)rr*1536 + c] =
                            __float22half2_rn(make_float2(acc[mt][nt][hh*2+0], acc[mt][nt][hh*2+1]));
                    }
                }
            } else {
                *(float2*)&C[(size_t)r0    *N + c] = make_float2(acc[mt][nt][0], acc[mt][nt][1]);
                *(float2*)&C[(size_t)(r0+8)*N + c] = make_float2(acc[mt][nt][2], acc[mt][nt][3]);
            }
        }
    }
}

// ---------------- split-K reduce + bias ----------------
__global__ void reduce_kernel(float* __restrict__ out, const float* __restrict__ bias)
{
    int i = blockIdx.x*256 + threadIdx.x;
    if (i >= ROWS*HIDDEN/4) return;
    size_t off = (size_t)i*4;
    const size_t stride = (size_t)ROWS*HIDDEN;
    float4 a = *(const float4*)&g_part[off];
    float4 b = *(const float4*)&g_part[off + stride];
    float4 c = *(const float4*)&g_part[off + 2*stride];
    float4 d = *(const float4*)&g_part[off + 3*stride];
    int col = (int)(off & (HIDDEN-1));
    float4 bb = *(const float4*)&bias[col];
    float4 r;
    r.x = a.x + b.x + c.x + d.x + bb.x;
    r.y = a.y + b.y + c.y + d.y + bb.y;
    r.z = a.z + b.z + c.z + d.z + bb.z;
    r.w = a.w + b.w + c.w + d.w + bb.w;
    *(float4*)&out[off] = r;
}

// ---------------- flash attention: fp16 mma, split-K, f16x2 exp2 softmax ------
#define QST 72
#define QTILE (64*QST)
__global__ void __launch_bounds__(128, 4) attn_mma_kernel()
{
    const int qb     = blockIdx.y;
    const int ntiles = qb + 1;
    const int chunk  = blockIdx.x;
    const int start  = chunk*CHUNK_TILES;
    if (start >= ntiles) return;
    const int end    = min(start + CHUNK_TILES, ntiles);
    const int nc     = (ntiles + CHUNK_TILES - 1) / CHUNK_TILES;
    const int nt_loc = end - start;

    extern __shared__ __half asm_[];
    const int bz = blockIdx.z;
    const int h  = bz & 7;
    const int b  = bz >> 3;
    const int q0 = qb*64;
    const int tid  = threadIdx.x;
    const int warp = tid >> 5;
    const int lane = tid & 31;
    const int gq = lane >> 2;
    const int qd = lane & 3;
    const int lrow  = lane & 15;
    const int lcol8 = (lane >> 4) * 8;
    const int vrow  = (lane & 7) + ((lane >> 3) & 1) * 8;

    const float scale2 = 0.125f * LOG2E;
    const float slope2 = exp2f(-(float)(h+1)) * LOG2E;

    const uint32_t q_u = (uint32_t)__cvta_generic_to_shared(asm_);
    const uint32_t k_u[2] = { q_u + (uint32_t)QTILE*2, q_u + (uint32_t)(3*QTILE)*2 };
    const uint32_t v_u[2] = { q_u + (uint32_t)(2*QTILE)*2, q_u + (uint32_t)(4*QTILE)*2 };

    const int cr  = tid >> 3;
    const int cc8 = (tid & 7) * 8;

    {
        const __half* qb_ = g_projh + (size_t)(b*SEQ + q0 + cr)*1536 + h*HD + cc8;
        #pragma unroll
        for (int i = 0; i < 4; i++)
            cp16(q_u + (uint32_t)((cr + i*16)*QST + cc8)*2, qb_ + (size_t)i*16*1536);
        const __half* kv = g_projh + (size_t)(b*SEQ + start*64 + cr)*1536 + h*HD + cc8;
        #pragma unroll
        for (int i = 0; i < 4; i++) {
            cp16(k_u[0] + (uint32_t)((cr + i*16)*QST + cc8)*2, kv + (size_t)i*16*1536 + 512);
            cp16(v_u[0] + (uint32_t)((cr + i*16)*QST + cc8)*2, kv + (size_t)i*16*1536 + 1024);
        }
        asm volatile("cp.async.commit_group;");
    }
    if (nt_loc > 1) {
        const __half* kv = g_projh + (size_t)(b*SEQ + (start+1)*64 + cr)*1536 + h*HD + cc8;
        #pragma unroll
        for (int i = 0; i < 4; i++) {
            cp16(k_u[1] + (uint32_t)((cr + i*16)*QST + cc8)*2, kv + (size_t)i*16*1536 + 512);
            cp16(v_u[1] + (uint32_t)((cr + i*16)*QST + cc8)*2, kv + (size_t)i*16*1536 + 1024);
        }
    }
    asm volatile("cp.async.commit_group;");
    asm volatile("cp.async.wait_group 1;");
    __syncthreads();

    uint32_t qf[4][4];
    #pragma unroll
    for (int kt = 0; kt < 4; kt++)
        ldsm4(qf[kt], q_u + (uint32_t)((warp*16 + lrow)*QST + kt*16 + lcol8)*2);

    float o[8][4];
    #pragma unroll
    for (int t = 0; t < 8; t++) { o[t][0]=0.f; o[t][1]=0.f; o[t][2]=0.f; o[t][3]=0.f; }
    float m0 = -INFINITY, m1 = -INFINITY, l0 = 0.f, l1 = 0.f;
    const int i0 = q0 + warp*16 + gq;
    const int i1 = i0 + 8;

    for (int lt = 0; lt < nt_loc; lt++) {
        const int j0 = (start + lt)*64;
        const int st = lt & 1;

        float s[8][4];
        #pragma unroll
        for (int t = 0; t < 8; t++) { s[t][0]=0.f; s[t][1]=0.f; s[t][2]=0.f; s[t][3]=0.f; }
        #pragma unroll
        for (int kt = 0; kt < 4; kt++) {
            #pragma unroll
            for (int p = 0; p < 4; p++) {
                uint32_t bf[4];
                ldsm4(bf, k_u[st] + (uint32_t)((p*16 + lrow)*QST + kt*16 + lcol8)*2);
                mma_f16(s[2*p],   qf[kt], bf[0], bf[2]);
                mma_f16(s[2*p+1], qf[kt], bf[1], bf[3]);
            }
        }

        float rm0 = -INFINITY, rm1 = -INFINITY;
        #pragma unroll
        for (int nt = 0; nt < 8; nt++) {
            int j = j0 + nt*8 + 2*qd;
            s[nt][0] = (j   <= i0) ? fmaf(s[nt][0], scale2, slope2*(float)j    ) : -1e30f;
            s[nt][1] = (j+1 <= i0) ? fmaf(s[nt][1], scale2, slope2*(float)(j+1)) : -1e30f;
            s[nt][2] = (j   <= i1) ? fmaf(s[nt][2], scale2, slope2*(float)j    ) : -1e30f;
            s[nt][3] = (j+1 <= i1) ? fmaf(s[nt][3], scale2, slope2*(float)(j+1)) : -1e30f;
            rm0 = fmaxf(rm0, fmaxf(s[nt][0], s[nt][1]));
            rm1 = fmaxf(rm1, fmaxf(s[nt][2], s[nt][3]));
        }
        rm0 = fmaxf(rm0, __shfl_xor_sync(0xffffffffu, rm0, 1));
        rm0 = fmaxf(rm0, __shfl_xor_sync(0xffffffffu, rm0, 2));
        rm1 = fmaxf(rm1, __shfl_xor_sync(0xffffffffu, rm1, 1));
        rm1 = fmaxf(rm1, __shfl_xor_sync(0xffffffffu, rm1, 2));
        float nm0 = fmaxf(m0, rm0), nm1 = fmaxf(m1, rm1);
        float c0 = exp2f(m0 - nm0), c1 = exp2f(m1 - nm1);
        m0 = nm0; m1 = nm1;

        uint32_t ph[8][2];
        float ps0 = 0.f, ps1 = 0.f;
        #pragma unroll
        for (int nt = 0; nt < 8; nt++) {
            ph[nt][0] = exp2_f16x2(s[nt][0] - nm0, s[nt][1] - nm0);
            ph[nt][1] = exp2_f16x2(s[nt][2] - nm1, s[nt][3] - nm1);
            float2 f0 = __half22float2(*(__half2*)&ph[nt][0]);
            float2 f1 = __half22float2(*(__half2*)&ph[nt][1]);
            ps0 += f0.x + f0.y;
            ps1 += f1.x + f1.y;
            o[nt][0] *= c0; o[nt][1] *= c0; o[nt][2] *= c1; o[nt][3] *= c1;
        }
        ps0 += __shfl_xor_sync(0xffffffffu, ps0, 1);
        ps0 += __shfl_xor_sync(0xffffffffu, ps0, 2);
        ps1 += __shfl_xor_sync(0xffffffffu, ps1, 1);
        ps1 += __shfl_xor_sync(0xffffffffu, ps1, 2);
        l0 = l0*c0 + ps0;
        l1 = l1*c1 + ps1;

        #pragma unroll
        for (int c = 0; c < 4; c++) {
            uint32_t pa[4];
            pa[0] = ph[2*c][0];
            pa[1] = ph[2*c][1];
            pa[2] = ph[2*c+1][0];
            pa[3] = ph[2*c+1][1];
            #pragma unroll
            for (int p = 0; p < 4; p++) {
                uint32_t bf[4];
                ldsm4t(bf, v_u[st] + (uint32_t)((c*16 + vrow)*QST + p*16 + lcol8)*2);
                mma_f16(o[2*p],   pa, bf[0], bf[1]);
                mma_f16(o[2*p+1], pa, bf[2], bf[3]);
            }
        }
        __syncthreads();

        if (lt + 1 < nt_loc) {
            if (lt + 2 < nt_loc) {
                const int jn = (start + lt + 2)*64;
                const __half* kv = g_projh + (size_t)(b*SEQ + jn + cr)*1536 + h*HD + cc8;
                #pragma unroll
                for (int i = 0; i < 4; i++) {
                    cp16(k_u[st] + (uint32_t)((cr + i*16)*QST + cc8)*2, kv + (size_t)i*16*1536 + 512);
                    cp16(v_u[st] + (uint32_t)((cr + i*16)*QST + cc8)*2, kv + (size_t)i*16*1536 + 1024);
                }
            }
            asm volatile("cp.async.commit_group;");
            asm volatile("cp.async.wait_group 1;");
            __syncthreads();
        }
    }

    if (nc == 1) {
        float inv0 = 1.f / l0, inv1 = 1.f / l1;
        size_t ob0 = (size_t)(b*SEQ + i0)*VP + h*HD;
        size_t ob1 = (size_t)(b*SEQ + i1)*VP + h*HD;
        #pragma unroll
        for (int nt = 0; nt < 8; nt++) {
            int cl = nt*8 + 2*qd;
            *(__half2*)&g_cath[ob0 + cl] = __float22half2_rn(make_float2(o[nt][0]*inv0, o[nt][1]*inv0));
            *(__half2*)&g_cath[ob1 + cl] = __float22half2_rn(make_float2(o[nt][2]*inv1, o[nt][3]*inv1));
        }
    } else {
        const int pb = (bz*32 + qb)*4 + chunk;
        float* po = g_part + (size_t)pb*4096;
        const int r0 = warp*16 + gq;
        const int r1 = r0 + 8;
        #pragma unroll
        for (int nt = 0; nt < 8; nt++) {
            int cl = nt*8 + 2*qd;
            *(float2*)&po[r0*64 + cl] = make_float2(o[nt][0], o[nt][1]);
            *(float2*)&po[r1*64 + cl] = make_float2(o[nt][2], o[nt][3]);
        }
        if (qd == 0) {
            float* ml = g_ml + (size_t)pb*128;
            ml[r0] = m0;  ml[64 + r0] = l0;    // m in log2 domain
            ml[r1] = m1;  ml[64 + r1] = l1;
        }
    }
}

// ---------------- attention combine (qb >= 8) ----------------
__global__ void __launch_bounds__(256) attn_combine_kernel()
{
    const int qb = 8 + blockIdx.x;
    const int bz = blockIdx.y;
    const int h  = bz & 7;
    const int b  = bz >> 3;
    const int nc = qb/CHUNK_TILES + 1;
    const int tid = threadIdx.x;
    const int row = tid >> 2;
    const int dg  = (tid & 3) << 4;

    const int pb0 = (bz*32 + qb)*4;
    float mc[4], lc[4];
    float M = -INFINITY;
    for (int c = 0; c < nc; c++) {
        const float* ml = g_ml + (size_t)(pb0 + c)*128;
        mc[c] = ml[row];
        lc[c] = ml[64 + row];
        M = fmaxf(M, mc[c]);
    }
    float L = 0.f;
    float acc[16];
    #pragma unroll
    for (int i = 0; i < 16; i++) acc[i] = 0.f;
    for (int c = 0; c < nc; c++) {
        float w = exp2f(mc[c] - M);      // log2-domain m
        L += lc[c]*w;
        const float* po = g_part + (size_t)(pb0 + c)*4096 + row*64 + dg;
        #pragma unroll
        for (int i = 0; i < 4; i++) {
            float4 v = *(const float4*)&po[i*4];
            acc[i*4+0] += v.x*w; acc[i*4+1] += v.y*w;
            acc[i*4+2] += v.z*w; acc[i*4+3] += v.w*w;
        }
    }
    float inv = 1.f / L;
    __half* dst = g_cath + (size_t)(b*SEQ + qb*64 + row)*VP + h*HD + dg;
    #pragma unroll
    for (int j = 0; j < 8; j++)
        *(__half2*)&dst[j*2] = __float22half2_rn(make_float2(acc[2*j]*inv, acc[2*j+1]*inv));
}

// ---------------- launch ----------------
extern "C" void kernel_launch(void* const* d_in, const int* in_sizes, int n_in,
                              void* d_out, int out_size)
{
    (void)in_sizes; (void)n_in; (void)out_size;
    const float* x     = (const float*)d_in[0];
    const float* gamma = (const float*)d_in[1];
    const float* beta  = (const float*)d_in[2];
    const float* w_in  = (const float*)d_in[3];
    const float* w_out = (const float*)d_in[4];
    const float* b_out = (const float*)d_in[5];
    float* out = (float*)d_out;

    __half *p_xth, *p_w1t, *p_w2t, *p_cath;
    float *p_part;
    cudaGetSymbolAddress((void**)&p_xth,  g_xth);
    cudaGetSymbolAddress((void**)&p_w1t,  g_w1t);
    cudaGetSymbolAddress((void**)&p_w2t,  g_w2t);
    cudaGetSymbolAddress((void**)&p_cath, g_cath);
    cudaGetSymbolAddress((void**)&p_part, g_part);

    weights_cvt_kernel<<<W1_BLOCKS + W2_BLOCKS, 256>>>(w_in, w_out, p_w1t, p_w2t);

    ln_kernel<<<ROWS, 128>>>(x, gamma, beta);
    featscan_kernel<<<BATCH*64 + (ROWS*16 + 255)/256, 256>>>();

    int gemm_smem = 2*NSTG*ASTG*2;                          // 61440
    cudaFuncSetAttribute(hgemm_kernel<1>, cudaFuncAttributeMaxDynamicSharedMemorySize, gemm_smem);
    cudaFuncSetAttribute(hgemm_kernel<2>, cudaFuncAttributeMaxDynamicSharedMemorySize, gemm_smem);

    dim3 g1(QKVP/128, ROWS/128);     // (28, 32)
    hgemm_kernel<1><<<g1, 256, gemm_smem>>>(p_xth, p_w1t, nullptr, HIDDEN, HIDDEN, HIDDEN, QKVP);

    int attn_smem = 5*QTILE*2;                              // 46080
    cudaFuncSetAttribute(attn_mma_kernel, cudaFuncAttributeMaxDynamicSharedMemorySize, attn_smem);
    attn_mma_kernel<<<dim3(4, SEQ/64, BATCH*HEADS), 128, attn_smem>>>();
    attn_combine_kernel<<<dim3(24, BATCH*HEADS), 256>>>();

    dim3 g2(HIDDEN/128, ROWS/128, KSPLITS);  // (4, 32, 4)
    hgemm_kernel<2><<<g2, 256, gemm_smem>>>(p_cath, p_w2t, p_part, KSPLIT, VP, VP, HIDDEN);
    reduce_kernel<<<(ROWS*HIDDEN/4 + 255)/256, 256>>>(out, b_out);
}

// round 16
// speedup vs baseline: 1.2595x; 1.0593x over previous
#include <cuda_runtime.h>
#include <cuda_fp16.h>
#include <math.h>
#include <stdint.h>

#define BATCH  2
#define SEQ    2048
#define ROWS   (BATCH*SEQ)     // 4096
#define HIDDEN 512
#define QKVP   3584
#define VP     2560
#define HEADS  8
#define HD     64
#define KSPLITS 4
#define KSPLIT  (VP/KSPLITS)   // 640
#define CHUNK_TILES 8
#define LOG2E  1.4426950408889634f

// ---------------- scratch ----------------
__device__ float  g_xn[(size_t)ROWS*HIDDEN];
__device__ __align__(128) __half g_xth [(size_t)ROWS*HIDDEN];
__device__ __align__(128) __half g_projh[(size_t)ROWS*1536];     // q,k,v
__device__ __align__(128) __half g_cath[(size_t)ROWS*VP];
__device__ __align__(128) __half g_w1t[(size_t)QKVP*HIDDEN];     // [N][K]
__device__ __align__(128) __half g_w2t[(size_t)HIDDEN*VP];       // [N][K]
__device__ float  g_part[(size_t)KSPLITS*ROWS*HIDDEN];           // attn partials, then split-K partials
__device__ float  g_ml[(size_t)BATCH*HEADS*32*4*128];

// ---------------- helpers ----------------
__device__ __forceinline__ void mma_f16(float* d, const uint32_t* a, uint32_t b0, uint32_t b1) {
    asm volatile("mma.sync.aligned.m16n8k16.row.col.f32.f16.f16.f32 "
        "{%0,%1,%2,%3}, {%4,%5,%6,%7}, {%8,%9}, {%0,%1,%2,%3};"
        : "+f"(d[0]), "+f"(d[1]), "+f"(d[2]), "+f"(d[3])
        : "r"(a[0]), "r"(a[1]), "r"(a[2]), "r"(a[3]), "r"(b0), "r"(b1));
}
__device__ __forceinline__ void ldsm4(uint32_t* r, uint32_t a) {
    asm volatile("ldmatrix.sync.aligned.m8n8.x4.shared.b16 {%0,%1,%2,%3}, [%4];"
        : "=r"(r[0]), "=r"(r[1]), "=r"(r[2]), "=r"(r[3]) : "r"(a));
}
__device__ __forceinline__ void ldsm4t(uint32_t* r, uint32_t a) {
    asm volatile("ldmatrix.sync.aligned.m8n8.x4.trans.shared.b16 {%0,%1,%2,%3}, [%4];"
        : "=r"(r[0]), "=r"(r[1]), "=r"(r[2]), "=r"(r[3]) : "r"(a));
}
__device__ __forceinline__ void cp16(uint32_t dst, const void* src) {
    asm volatile("cp.async.cg.shared.global [%0], [%1], 16;" :: "r"(dst), "l"(src));
}
__device__ __forceinline__ uint32_t exp2_f16x2(float lo, float hi) {
    uint32_t r;
    asm("{\n\t.reg .b32 t;\n\t"
        "cvt.rn.f16x2.f32 t, %2, %1;\n\t"
        "ex2.approx.f16x2 t, t;\n\t"
        "mov.b32 %0, t;\n\t}"
        : "=r"(r) : "f"(lo), "f"(hi));
    return r;
}

// ---------------- merged weight transpose+cvt ----------------
__device__ __forceinline__ void trans_tile(const float* __restrict__ src,
                                           __half* __restrict__ dst,
                                           int K, int N, int k0, int n0)
{
    __shared__ __half t[32][33];
    int tx = threadIdx.x & 31, ty = threadIdx.x >> 5;
    #pragma unroll
    for (int i = 0; i < 32; i += 8)
        t[ty+i][tx] = __float2half_rn(src[(size_t)(k0+ty+i)*N + n0+tx]);
    __syncthreads();
    #pragma unroll
    for (int i = 0; i < 32; i += 8)
        dst[(size_t)(n0+ty+i)*K + k0+tx] = t[tx][ty+i];
}
#define W1_BLOCKS ((HIDDEN/32)*(QKVP/32))   // 1792
#define W2_BLOCKS ((VP/32)*(HIDDEN/32))     // 1280
__global__ void __launch_bounds__(256) weights_cvt_kernel(
    const float* __restrict__ w_in, const float* __restrict__ w_out,
    __half* __restrict__ w1t, __half* __restrict__ w2t)
{
    int bid = blockIdx.x;
    if (bid < W1_BLOCKS) {
        int bx = bid & 15, by = bid >> 4;
        trans_tile(w_in, w1t, HIDDEN, QKVP, bx*32, by*32);
    } else {
        int b2 = bid - W1_BLOCKS;
        int bx = b2 % 80, by = b2 / 80;
        trans_tile(w_out, w2t, VP, HIDDEN, bx*32, by*32);
    }
}

// ---------------- LayerNorm (+ fused ident copy), vectorized ----------------
__global__ void __launch_bounds__(128) ln_kernel(const float* __restrict__ x,
                                                 const float* __restrict__ gamma,
                                                 const float* __restrict__ beta)
{
    int row = blockIdx.x;
    int tid = threadIdx.x;
    int c0  = tid*4;
    const float* xr = x + (size_t)row*HIDDEN;
    float4 v = *(const float4*)&xr[c0];
    float s = v.x + v.y + v.z + v.w;
    __shared__ float red[4];
    #pragma unroll
    for (int o = 16; o > 0; o >>= 1) s += __shfl_xor_sync(0xffffffffu, s, o);
    if ((tid & 31) == 0) red[tid >> 5] = s;
    __syncthreads();
    float mu = (red[0]+red[1]+red[2]+red[3]) * (1.f/HIDDEN);
    float vs = (v.x-mu)*(v.x-mu) + (v.y-mu)*(v.y-mu) + (v.z-mu)*(v.z-mu) + (v.w-mu)*(v.w-mu);
    #pragma unroll
    for (int o = 16; o > 0; o >>= 1) vs += __shfl_xor_sync(0xffffffffu, vs, o);
    __syncthreads();
    if ((tid & 31) == 0) red[tid >> 5] = vs;
    __syncthreads();
    float var  = (red[0]+red[1]+red[2]+red[3]) * (1.f/HIDDEN);
    float rstd = rsqrtf(var + 1e-5f);
    float4 g = *(const float4*)&gamma[c0];
    float4 bt = *(const float4*)&beta[c0];
    float4 xn;
    xn.x = (v.x-mu)*rstd*g.x + bt.x;
    xn.y = (v.y-mu)*rstd*g.y + bt.y;
    xn.z = (v.z-mu)*rstd*g.z + bt.z;
    xn.w = (v.w-mu)*rstd*g.w + bt.w;
    *(float4*)&g_xn[(size_t)row*HIDDEN + c0] = xn;
    if (c0 < 320) {
        __half2 h0 = __float22half2_rn(make_float2(xn.x, xn.y));
        __half2 h1 = __float22half2_rn(make_float2(xn.z, xn.w));
        uint2 u = make_uint2(*(uint32_t*)&h0, *(uint32_t*)&h1);
        *(uint2*)&g_xth[(size_t)row*HIDDEN + c0] = u;
    }
}

// ---------------- merged feat + scan ----------------
__device__ void scan_body(int bc)
{
    int b   = bc >> 6;
    int ch  = 320 + (bc & 63);
    int tid = threadIdx.x;
    int row0 = b*SEQ + tid*8;
    float y[8];
    #pragma unroll
    for (int i = 0; i < 8; i++) y[i] = 5.f * g_xn[(size_t)(row0+i)*HIDDEN + ch];
    float m = -INFINITY, s = 0.f;
    #pragma unroll
    for (int i = 0; i < 8; i++) {
        float M = fmaxf(m, y[i]);
        s = s*expf(m - M) + expf(y[i] - M);
        m = M;
    }
    __shared__ float sm[256], ss[256];
    sm[tid] = m; ss[tid] = s;
    __syncthreads();
    for (int off = 1; off < 256; off <<= 1) {
        float pm = 0.f, ps = 0.f;
        bool act = (tid >= off);
        if (act) { pm = sm[tid-off]; ps = ss[tid-off]; }
        __syncthreads();
        if (act) {
            float M = fmaxf(pm, m);
            s = ps*expf(pm - M) + s*expf(m - M);
            m = M;
            sm[tid] = m; ss[tid] = s;
        }
        __syncthreads();
    }
    float pm = -INFINITY, ps = 0.f;
    if (tid > 0) { pm = sm[tid-1]; ps = ss[tid-1]; }
    #pragma unroll
    for (int i = 0; i < 8; i++) {
        float M = fmaxf(pm, y[i]);
        ps = ps*expf(pm - M) + expf(y[i] - M);
        pm = M;
        g_xth[(size_t)(row0+i)*HIDDEN + ch] = __float2half_rn((pm + logf(ps)) * 0.2f);
    }
}
__device__ void feat_body(int fb)
{
    int idx = fb*256 + threadIdx.x;
    if (idx >= ROWS*16) return;
    int chunk = idx & 15;
    int row   = idx >> 4;
    int c     = 384 + chunk*8;
    int i     = row & (SEQ-1);
    int sh    = (c < 448) ? 1 : 2;
    float4 v0 = make_float4(0.f,0.f,0.f,0.f), v1 = v0;
    if (i >= sh) {
        const float* src = &g_xn[(size_t)(row-sh)*HIDDEN + c];
        v0 = *(const float4*)src;
        v1 = *(const float4*)(src+4);
    }
    __half2 p0 = __float22half2_rn(make_float2(v0.x, v0.y));
    __half2 p1 = __float22half2_rn(make_float2(v0.z, v0.w));
    __half2 p2 = __float22half2_rn(make_float2(v1.x, v1.y));
    __half2 p3 = __float22half2_rn(make_float2(v1.z, v1.w));
    uint4 u = make_uint4(*(uint32_t*)&p0, *(uint32_t*)&p1, *(uint32_t*)&p2, *(uint32_t*)&p3);
    *(uint4*)&g_xth[(size_t)row*HIDDEN + c] = u;
}
__global__ void __launch_bounds__(256) featscan_kernel()
{
    if (blockIdx.x < BATCH*64) scan_body(blockIdx.x);
    else                       feat_body(blockIdx.x - BATCH*64);
}

// ---------------- fp16 tensor GEMM: compile-time dims, fully unrolled --------
#define AST 40                 // halves per row (80B: 5r mod 8 -> conflict-free ldsm)
#define ASTG (128*AST)
#define NSTG 3
template<int MODE>
__global__ void __launch_bounds__(256, 2) hgemm_kernel(
    const __half* __restrict__ A, const __half* __restrict__ B, float* __restrict__ C)
{
    constexpr int K_  = (MODE == 1) ? HIDDEN : KSPLIT;    // 512 / 640
    constexpr int LDA = (MODE == 1) ? HIDDEN : VP;        // 512 / 2560
    constexpr int LDB = (MODE == 1) ? HIDDEN : VP;        // 512 / 2560
    constexpr int N_  = (MODE == 1) ? QKVP   : HIDDEN;    // 3584 / 512
    constexpr int kTiles = K_ >> 5;                       // 16 / 20

    extern __shared__ __half hsm[];
    __half* As = hsm;
    __half* Bs = hsm + NSTG*ASTG;

    if (MODE == 2) {
        const int z = blockIdx.z;
        A += (size_t)z*K_;
        B += (size_t)z*K_;
        C += (size_t)z*ROWS*N_;
    }

    const int tid  = threadIdx.x;
    const int warp = tid >> 5;
    const int lane = tid & 31;
    const int gq = lane >> 2;
    const int qd = lane & 3;
    const int warp_m = (warp & 3) * 32;
    const int warp_n = (warp >> 2) * 64;
    const int m0 = blockIdx.y * 128;
    const int n0 = blockIdx.x * 128;
    const int lrow  = lane & 15;
    const int lcol8 = (lane >> 4) * 8;

    const int a_r  = tid >> 2;
    const int a_c8 = (tid & 3) * 8;

    const uint32_t as_u = (uint32_t)__cvta_generic_to_shared(As);
    const uint32_t bs_u = (uint32_t)__cvta_generic_to_shared(Bs);
    const uint32_t a_dst0 = as_u + (uint32_t)(a_r*AST + a_c8)*2;
    const uint32_t b_dst0 = bs_u + (uint32_t)(a_r*AST + a_c8)*2;

    // precomputed ldsm base addresses (stage/kk offsets fold to immediates)
    uint32_t a_ls[2], b_ls[4];
    #pragma unroll
    for (int mt = 0; mt < 2; mt++)
        a_ls[mt] = as_u + (uint32_t)((warp_m + mt*16 + lrow)*AST + lcol8)*2;
    #pragma unroll
    for (int p = 0; p < 4; p++)
        b_ls[p] = bs_u + (uint32_t)((warp_n + p*16 + lrow)*AST + lcol8)*2;

    const __half* Ag0 = A + (size_t)(m0 + a_r)*LDA + a_c8;
    const __half* Bg0 = B + (size_t)(n0 + a_r)*LDB + a_c8;

    #pragma unroll
    for (int s = 0; s < NSTG; s++) {
        #pragma unroll
        for (int i = 0; i < 2; i++) {
            cp16(a_dst0 + (uint32_t)(s*ASTG + i*64*AST)*2, Ag0 + (size_t)i*64*LDA + s*32);
            cp16(b_dst0 + (uint32_t)(s*ASTG + i*64*AST)*2, Bg0 + (size_t)i*64*LDB + s*32);
        }
        asm volatile("cp.async.commit_group;");
    }
    asm volatile("cp.async.wait_group %0;" :: "n"(NSTG-1));
    __syncthreads();

    float acc[2][8][4];
    #pragma unroll
    for (int mt = 0; mt < 2; mt++)
        #pragma unroll
        for (int nt = 0; nt < 8; nt++)
            #pragma unroll
            for (int i = 0; i < 4; i++) acc[mt][nt][i] = 0.f;

    #pragma unroll
    for (int t = 0; t < kTiles; t++) {
        const int stage = t % NSTG;                       // literal under full unroll
        #pragma unroll
        for (int kk = 0; kk < 2; kk++) {
            uint32_t af[2][4];
            #pragma unroll
            for (int mt = 0; mt < 2; mt++)
                ldsm4(af[mt], a_ls[mt] + (uint32_t)(stage*ASTG + kk*16)*2);
            #pragma unroll
            for (int p = 0; p < 4; p++) {
                uint32_t bf[4];
                ldsm4(bf, b_ls[p] + (uint32_t)(stage*ASTG + kk*16)*2);
                mma_f16(acc[0][2*p],   af[0], bf[0], bf[2]);
                mma_f16(acc[0][2*p+1], af[0], bf[1], bf[3]);
                mma_f16(acc[1][2*p],   af[1], bf[0], bf[2]);
                mma_f16(acc[1][2*p+1], af[1], bf[1], bf[3]);
            }
        }
        __syncthreads();                                  // stage consumed
        if (t + NSTG < kTiles) {                          // refill freed stage
            #pragma unroll
            for (int i = 0; i < 2; i++) {
                cp16(a_dst0 + (uint32_t)(stage*ASTG + i*64*AST)*2, Ag0 + (size_t)i*64*LDA + (t+NSTG)*32);
                cp16(b_dst0 + (uint32_t)(stage*ASTG + i*64*AST)*2, Bg0 + (size_t)i*64*LDB + (t+NSTG)*32);
            }
        }
        asm volatile("cp.async.commit_group;");
        asm volatile("cp.async.wait_group %0;" :: "n"(NSTG-1));   // tile t+1 landed
    }

    #pragma unroll
    for (int mt = 0; mt < 2; mt++) {
        const int r0 = m0 + warp_m + mt*16 + gq;
        #pragma unroll
        for (int nt = 0; nt < 8; nt++) {
            const int c = n0 + warp_n + nt*8 + 2*qd;
            if (MODE == 1) {
                if (c >= 1536) {
                    #pragma unroll
                    for (int hh = 0; hh < 2; hh++) {
                        int rr = r0 + hh*8;
                        float v0 = acc[mt][nt][hh*2+0], v1 = acc[mt][nt][hh*2+1];
                        float gl0 = 0.5f*v0*(1.f + erff(v0*0.70710678118654752f));
                        float gl1 = 0.5f*v1*(1.f + erff(v1*0.70710678118654752f));
                        *(__half2*)&g_cath[(size_t)rr*VP + (c - 1024)] =
                            __float22half2_rn(make_float2(gl0, gl1));
                    }
                } else {
                    #pragma unroll
                    for (int hh = 0; hh < 2; hh++) {
                        int rr = r0 + hh*8;
                        *(__half2*)&g_projh[(size_t)rr*1536 + c] =
                            __float22half2_rn(make_float2(acc[mt][nt][hh*2+0], acc[mt][nt][hh*2+1]));
                    }
                }
            } else {
                *(float2*)&C[(size_t)r0    *N_ + c] = make_float2(acc[mt][nt][0], acc[mt][nt][1]);
                *(float2*)&C[(size_t)(r0+8)*N_ + c] = make_float2(acc[mt][nt][2], acc[mt][nt][3]);
            }
        }
    }
}

// ---------------- split-K reduce + bias ----------------
__global__ void reduce_kernel(float* __restrict__ out, const float* __restrict__ bias)
{
    int i = blockIdx.x*256 + threadIdx.x;
    if (i >= ROWS*HIDDEN/4) return;
    size_t off = (size_t)i*4;
    const size_t stride = (size_t)ROWS*HIDDEN;
    float4 a = *(const float4*)&g_part[off];
    float4 b = *(const float4*)&g_part[off + stride];
    float4 c = *(const float4*)&g_part[off + 2*stride];
    float4 d = *(const float4*)&g_part[off + 3*stride];
    int col = (int)(off & (HIDDEN-1));
    float4 bb = *(const float4*)&bias[col];
    float4 r;
    r.x = a.x + b.x + c.x + d.x + bb.x;
    r.y = a.y + b.y + c.y + d.y + bb.y;
    r.z = a.z + b.z + c.z + d.z + bb.z;
    r.w = a.w + b.w + c.w + d.w + bb.w;
    *(float4*)&out[off] = r;
}

// ---------------- flash attention: fp16 mma, split-K, f16x2 exp2 softmax ------
#define QST 72
#define QTILE (64*QST)
__global__ void __launch_bounds__(128, 4) attn_mma_kernel()
{
    const int qb     = blockIdx.y;
    const int ntiles = qb + 1;
    const int chunk  = blockIdx.x;
    const int start  = chunk*CHUNK_TILES;
    if (start >= ntiles) return;
    const int end    = min(start + CHUNK_TILES, ntiles);
    const int nc     = (ntiles + CHUNK_TILES - 1) / CHUNK_TILES;
    const int nt_loc = end - start;

    extern __shared__ __half asm_[];
    const int bz = blockIdx.z;
    const int h  = bz & 7;
    const int b  = bz >> 3;
    const int q0 = qb*64;
    const int tid  = threadIdx.x;
    const int warp = tid >> 5;
    const int lane = tid & 31;
    const int gq = lane >> 2;
    const int qd = lane & 3;
    const int lrow  = lane & 15;
    const int lcol8 = (lane >> 4) * 8;
    const int vrow  = (lane & 7) + ((lane >> 3) & 1) * 8;

    const float scale2 = 0.125f * LOG2E;
    const float slope2 = exp2f(-(float)(h+1)) * LOG2E;

    const uint32_t q_u = (uint32_t)__cvta_generic_to_shared(asm_);
    const uint32_t k_u[2] = { q_u + (uint32_t)QTILE*2, q_u + (uint32_t)(3*QTILE)*2 };
    const uint32_t v_u[2] = { q_u + (uint32_t)(2*QTILE)*2, q_u + (uint32_t)(4*QTILE)*2 };

    const int cr  = tid >> 3;
    const int cc8 = (tid & 7) * 8;

    {
        const __half* qb_ = g_projh + (size_t)(b*SEQ + q0 + cr)*1536 + h*HD + cc8;
        #pragma unroll
        for (int i = 0; i < 4; i++)
            cp16(q_u + (uint32_t)((cr + i*16)*QST + cc8)*2, qb_ + (size_t)i*16*1536);
        const __half* kv = g_projh + (size_t)(b*SEQ + start*64 + cr)*1536 + h*HD + cc8;
        #pragma unroll
        for (int i = 0; i < 4; i++) {
            cp16(k_u[0] + (uint32_t)((cr + i*16)*QST + cc8)*2, kv + (size_t)i*16*1536 + 512);
            cp16(v_u[0] + (uint32_t)((cr + i*16)*QST + cc8)*2, kv + (size_t)i*16*1536 + 1024);
        }
        asm volatile("cp.async.commit_group;");
    }
    if (nt_loc > 1) {
        const __half* kv = g_projh + (size_t)(b*SEQ + (start+1)*64 + cr)*1536 + h*HD + cc8;
        #pragma unroll
        for (int i = 0; i < 4; i++) {
            cp16(k_u[1] + (uint32_t)((cr + i*16)*QST + cc8)*2, kv + (size_t)i*16*1536 + 512);
            cp16(v_u[1] + (uint32_t)((cr + i*16)*QST + cc8)*2, kv + (size_t)i*16*1536 + 1024);
        }
    }
    asm volatile("cp.async.commit_group;");
    asm volatile("cp.async.wait_group 1;");
    __syncthreads();

    uint32_t qf[4][4];
    #pragma unroll
    for (int kt = 0; kt < 4; kt++)
        ldsm4(qf[kt], q_u + (uint32_t)((warp*16 + lrow)*QST + kt*16 + lcol8)*2);

    float o[8][4];
    #pragma unroll
    for (int t = 0; t < 8; t++) { o[t][0]=0.f; o[t][1]=0.f; o[t][2]=0.f; o[t][3]=0.f; }
    float m0 = -INFINITY, m1 = -INFINITY, l0 = 0.f, l1 = 0.f;
    const int i0 = q0 + warp*16 + gq;
    const int i1 = i0 + 8;

    for (int lt = 0; lt < nt_loc; lt++) {
        const int j0 = (start + lt)*64;
        const int st = lt & 1;

        float s[8][4];
        #pragma unroll
        for (int t = 0; t < 8; t++) { s[t][0]=0.f; s[t][1]=0.f; s[t][2]=0.f; s[t][3]=0.f; }
        #pragma unroll
        for (int kt = 0; kt < 4; kt++) {
            #pragma unroll
            for (int p = 0; p < 4; p++) {
                uint32_t bf[4];
                ldsm4(bf, k_u[st] + (uint32_t)((p*16 + lrow)*QST + kt*16 + lcol8)*2);
                mma_f16(s[2*p],   qf[kt], bf[0], bf[2]);
                mma_f16(s[2*p+1], qf[kt], bf[1], bf[3]);
            }
        }

        float rm0 = -INFINITY, rm1 = -INFINITY;
        #pragma unroll
        for (int nt = 0; nt < 8; nt++) {
            int j = j0 + nt*8 + 2*qd;
            s[nt][0] = (j   <= i0) ? fmaf(s[nt][0], scale2, slope2*(float)j    ) : -1e30f;
            s[nt][1] = (j+1 <= i0) ? fmaf(s[nt][1], scale2, slope2*(float)(j+1)) : -1e30f;
            s[nt][2] = (j   <= i1) ? fmaf(s[nt][2], scale2, slope2*(float)j    ) : -1e30f;
            s[nt][3] = (j+1 <= i1) ? fmaf(s[nt][3], scale2, slope2*(float)(j+1)) : -1e30f;
            rm0 = fmaxf(rm0, fmaxf(s[nt][0], s[nt][1]));
            rm1 = fmaxf(rm1, fmaxf(s[nt][2], s[nt][3]));
        }
        rm0 = fmaxf(rm0, __shfl_xor_sync(0xffffffffu, rm0, 1));
        rm0 = fmaxf(rm0, __shfl_xor_sync(0xffffffffu, rm0, 2));
        rm1 = fmaxf(rm1, __shfl_xor_sync(0xffffffffu, rm1, 1));
        rm1 = fmaxf(rm1, __shfl_xor_sync(0xffffffffu, rm1, 2));
        float nm0 = fmaxf(m0, rm0), nm1 = fmaxf(m1, rm1);
        float c0 = exp2f(m0 - nm0), c1 = exp2f(m1 - nm1);
        m0 = nm0; m1 = nm1;

        uint32_t ph[8][2];
        float ps0 = 0.f, ps1 = 0.f;
        #pragma unroll
        for (int nt = 0; nt < 8; nt++) {
            ph[nt][0] = exp2_f16x2(s[nt][0] - nm0, s[nt][1] - nm0);
            ph[nt][1] = exp2_f16x2(s[nt][2] - nm1, s[nt][3] - nm1);
            float2 f0 = __half22float2(*(__half2*)&ph[nt][0]);
            float2 f1 = __half22float2(*(__half2*)&ph[nt][1]);
            ps0 += f0.x + f0.y;
            ps1 += f1.x + f1.y;
            o[nt][0] *= c0; o[nt][1] *= c0; o[nt][2] *= c1; o[nt][3] *= c1;
        }
        ps0 += __shfl_xor_sync(0xffffffffu, ps0, 1);
        ps0 += __shfl_xor_sync(0xffffffffu, ps0, 2);
        ps1 += __shfl_xor_sync(0xffffffffu, ps1, 1);
        ps1 += __shfl_xor_sync(0xffffffffu, ps1, 2);
        l0 = l0*c0 + ps0;
        l1 = l1*c1 + ps1;

        #pragma unroll
        for (int c = 0; c < 4; c++) {
            uint32_t pa[4];
            pa[0] = ph[2*c][0];
            pa[1] = ph[2*c][1];
            pa[2] = ph[2*c+1][0];
            pa[3] = ph[2*c+1][1];
            #pragma unroll
            for (int p = 0; p < 4; p++) {
                uint32_t bf[4];
                ldsm4t(bf, v_u[st] + (uint32_t)((c*16 + vrow)*QST + p*16 + lcol8)*2);
                mma_f16(o[2*p],   pa, bf[0], bf[1]);
                mma_f16(o[2*p+1], pa, bf[2], bf[3]);
            }
        }
        __syncthreads();

        if (lt + 1 < nt_loc) {
            if (lt + 2 < nt_loc) {
                const int jn = (start + lt + 2)*64;
                const __half* kv = g_projh + (size_t)(b*SEQ + jn + cr)*1536 + h*HD + cc8;
                #pragma unroll
                for (int i = 0; i < 4; i++) {
                    cp16(k_u[st] + (uint32_t)((cr + i*16)*QST + cc8)*2, kv + (size_t)i*16*1536 + 512);
                    cp16(v_u[st] + (uint32_t)((cr + i*16)*QST + cc8)*2, kv + (size_t)i*16*1536 + 1024);
                }
            }
            asm volatile("cp.async.commit_group;");
            asm volatile("cp.async.wait_group 1;");
            __syncthreads();
        }
    }

    if (nc == 1) {
        float inv0 = 1.f / l0, inv1 = 1.f / l1;
        size_t ob0 = (size_t)(b*SEQ + i0)*VP + h*HD;
        size_t ob1 = (size_t)(b*SEQ + i1)*VP + h*HD;
        #pragma unroll
        for (int nt = 0; nt < 8; nt++) {
            int cl = nt*8 + 2*qd;
            *(__half2*)&g_cath[ob0 + cl] = __float22half2_rn(make_float2(o[nt][0]*inv0, o[nt][1]*inv0));
            *(__half2*)&g_cath[ob1 + cl] = __float22half2_rn(make_float2(o[nt][2]*inv1, o[nt][3]*inv1));
        }
    } else {
        const int pb = (bz*32 + qb)*4 + chunk;
        float* po = g_part + (size_t)pb*4096;
        const int r0 = warp*16 + gq;
        const int r1 = r0 + 8;
        #pragma unroll
        for (int nt = 0; nt < 8; nt++) {
            int cl = nt*8 + 2*qd;
            *(float2*)&po[r0*64 + cl] = make_float2(o[nt][0], o[nt][1]);
            *(float2*)&po[r1*64 + cl] = make_float2(o[nt][2], o[nt][3]);
        }
        if (qd == 0) {
            float* ml = g_ml + (size_t)pb*128;
            ml[r0] = m0;  ml[64 + r0] = l0;    // m in log2 domain
            ml[r1] = m1;  ml[64 + r1] = l1;
        }
    }
}

// ---------------- attention combine (qb >= 8) ----------------
__global__ void __launch_bounds__(256) attn_combine_kernel()
{
    const int qb = 8 + blockIdx.x;
    const int bz = blockIdx.y;
    const int h  = bz & 7;
    const int b  = bz >> 3;
    const int nc = qb/CHUNK_TILES + 1;
    const int tid = threadIdx.x;
    const int row = tid >> 2;
    const int dg  = (tid & 3) << 4;

    const int pb0 = (bz*32 + qb)*4;
    float mc[4], lc[4];
    float M = -INFINITY;
    for (int c = 0; c < nc; c++) {
        const float* ml = g_ml + (size_t)(pb0 + c)*128;
        mc[c] = ml[row];
        lc[c] = ml[64 + row];
        M = fmaxf(M, mc[c]);
    }
    float L = 0.f;
    float acc[16];
    #pragma unroll
    for (int i = 0; i < 16; i++) acc[i] = 0.f;
    for (int c = 0; c < nc; c++) {
        float w = exp2f(mc[c] - M);
        L += lc[c]*w;
        const float* po = g_part + (size_t)(pb0 + c)*4096 + row*64 + dg;
        #pragma unroll
        for (int i = 0; i < 4; i++) {
            float4 v = *(const float4*)&po[i*4];
            acc[i*4+0] += v.x*w; acc[i*4+1] += v.y*w;
            acc[i*4+2] += v.z*w; acc[i*4+3] += v.w*w;
        }
    }
    float inv = 1.f / L;
    __half* dst = g_cath + (size_t)(b*SEQ + qb*64 + row)*VP + h*HD + dg;
    #pragma unroll
    for (int j = 0; j < 8; j++)
        *(__half2*)&dst[j*2] = __float22half2_rn(make_float2(acc[2*j]*inv, acc[2*j+1]*inv));
}

// ---------------- launch ----------------
extern "C" void kernel_launch(void* const* d_in, const int* in_sizes, int n_in,
                              void* d_out, int out_size)
{
    (void)in_sizes; (void)n_in; (void)out_size;
    const float* x     = (const float*)d_in[0];
    const float* gamma = (const float*)d_in[1];
    const float* beta  = (const float*)d_in[2];
    const float* w_in  = (const float*)d_in[3];
    const float* w_out = (const float*)d_in[4];
    const float* b_out = (const float*)d_in[5];
    float* out = (float*)d_out;

    __half *p_xth, *p_w1t, *p_w2t, *p_cath;
    float *p_part;
    cudaGetSymbolAddress((void**)&p_xth,  g_xth);
    cudaGetSymbolAddress((void**)&p_w1t,  g_w1t);
    cudaGetSymbolAddress((void**)&p_w2t,  g_w2t);
    cudaGetSymbolAddress((void**)&p_cath, g_cath);
    cudaGetSymbolAddress((void**)&p_part, g_part);

    weights_cvt_kernel<<<W1_BLOCKS + W2_BLOCKS, 256>>>(w_in, w_out, p_w1t, p_w2t);

    ln_kernel<<<ROWS, 128>>>(x, gamma, beta);
    featscan_kernel<<<BATCH*64 + (ROWS*16 + 255)/256, 256>>>();

    int gemm_smem = 2*NSTG*ASTG*2;                          // 61440
    cudaFuncSetAttribute(hgemm_kernel<1>, cudaFuncAttributeMaxDynamicSharedMemorySize, gemm_smem);
    cudaFuncSetAttribute(hgemm_kernel<2>, cudaFuncAttributeMaxDynamicSharedMemorySize, gemm_smem);

    dim3 g1(QKVP/128, ROWS/128);     // (28, 32)
    hgemm_kernel<1><<<g1, 256, gemm_smem>>>(p_xth, p_w1t, nullptr);

    int attn_smem = 5*QTILE*2;                              // 46080
    cudaFuncSetAttribute(attn_mma_kernel, cudaFuncAttributeMaxDynamicSharedMemorySize, attn_smem);
    attn_mma_kernel<<<dim3(4, SEQ/64, BATCH*HEADS), 128, attn_smem>>>();
    attn_combine_kernel<<<dim3(24, BATCH*HEADS), 256>>>();

    dim3 g2(HIDDEN/128, ROWS/128, KSPLITS);  // (4, 32, 4)
    hgemm_kernel<2><<<g2, 256, gemm_smem>>>(p_cath, p_w2t, p_part);
    reduce_kernel<<<(ROWS*HIDDEN/4 + 255)/256, 256>>>(out, b_out);
}